// round 13
// baseline (speedup 1.0000x reference)
#include <cuda_runtime.h>
#include <cuda_bf16.h>
#include <math.h>
#include <stdint.h>

#define DIMV   5120
#define KVDIM  1536
#define NH     40
#define HD     128
#define L1V    9360
#define LAV    96
#define NBLK   6
#define NKV    16
#define HWQ    1560
#define K2     (3 * DIMV)
#define NCOLS  (NH * NKV)
#define K3P    (3 * NCOLS)
#define NUALL  (NBLK * NCOLS)

// ---------------- scratch ----------------------------------------------------
__device__ float g_k[(size_t)LAV * DIMV];
__device__ float g_v[(size_t)LAV * DIMV];
__device__ float g_vtg[(size_t)NBLK * DIMV * NCOLS];
__device__ float g_cb[NUALL];
__device__ float g_ss[L1V];
__device__ __nv_bfloat16 g_xb[(size_t)L1V * DIMV];
__device__ __nv_bfloat16 g_wb[(size_t)DIMV * DIMV];
__device__ __nv_bfloat16 g_x3[(size_t)L1V * K2];
__device__ __nv_bfloat16 g_u3[(size_t)NUALL * K2];
__device__ __nv_bfloat16 g_p3[(size_t)L1V * K3P];
__device__ __nv_bfloat16 g_vt3[(size_t)NBLK * DIMV * K3P];

// ---------------- helpers ----------------------------------------------------
__device__ __forceinline__ uint32_t smem_u32(const void* p) {
    uint32_t a;
    asm("{ .reg .u64 t; cvta.to.shared.u64 t, %1; cvt.u32.u64 %0, t; }" : "=r"(a) : "l"(p));
    return a;
}
__device__ __forceinline__ void cp16(uint32_t dst, const void* src, int srcsize) {
    asm volatile("cp.async.cg.shared.global [%0], [%1], 16, %2;"
                 :: "r"(dst), "l"(src), "r"(srcsize) : "memory");
}
// pack two probabilities as split-3 (hi,lo,hi) -> 6 bf16 = 3 u32 stores
__device__ __forceinline__ void st_p3pair(__nv_bfloat16* d, float a, float b) {
    __nv_bfloat16 ah = __float2bfloat16(a);
    __nv_bfloat16 al = __float2bfloat16(a - __bfloat162float(ah));
    __nv_bfloat16 bh = __float2bfloat16(b);
    __nv_bfloat16 bl = __float2bfloat16(b - __bfloat162float(bh));
    union { __nv_bfloat16 h[6]; uint32_t u[3]; } o;
    o.h[0] = ah; o.h[1] = al; o.h[2] = ah;
    o.h[3] = bh; o.h[4] = bl; o.h[5] = bh;
    uint32_t* du = (uint32_t*)d;
    du[0] = o.u[0]; du[1] = o.u[1]; du[2] = o.u[2];
}

// ---------------------------------------------------------------------------
// converters
// ---------------------------------------------------------------------------
__global__ void __launch_bounds__(256)
cvt_x_fused(const float* __restrict__ X, __nv_bfloat16* __restrict__ XB,
            __nv_bfloat16* __restrict__ X3, size_t n8)
{
    size_t i = (size_t)blockIdx.x * blockDim.x + threadIdx.x;
    const size_t stride = (size_t)gridDim.x * blockDim.x;
    for (; i < n8; i += stride) {
        const float4* src = (const float4*)X + i * 2;
        float4 v0 = src[0], v1 = src[1];
        float f[8] = {v0.x, v0.y, v0.z, v0.w, v1.x, v1.y, v1.z, v1.w};
        union { __nv_bfloat16 h[8];  uint4 u; }    ob;
        union { __nv_bfloat16 h[24]; uint4 u[3]; } o3;
#pragma unroll
        for (int j = 0; j < 8; j++) {
            __nv_bfloat16 hi = __float2bfloat16(f[j]);
            __nv_bfloat16 lo = __float2bfloat16(f[j] - __bfloat162float(hi));
            ob.h[j] = hi;
            o3.h[3*j] = hi; o3.h[3*j+1] = lo; o3.h[3*j+2] = hi;
        }
        ((uint4*)XB)[i] = ob.u;
        uint4* dst = (uint4*)(X3 + i * 24);
        dst[0] = o3.u[0]; dst[1] = o3.u[1]; dst[2] = o3.u[2];
    }
}

__global__ void __launch_bounds__(256)
cvt_bf16(const float* __restrict__ X, __nv_bfloat16* __restrict__ Y, size_t n8)
{
    size_t i = (size_t)blockIdx.x * blockDim.x + threadIdx.x;
    const size_t stride = (size_t)gridDim.x * blockDim.x;
    for (; i < n8; i += stride) {
        const float4* src = (const float4*)X + i * 2;
        float4 v0 = src[0], v1 = src[1];
        union { __nv_bfloat162 h[4]; uint4 u; } o;
        o.h[0] = __nv_bfloat162(__float2bfloat16(v0.x), __float2bfloat16(v0.y));
        o.h[1] = __nv_bfloat162(__float2bfloat16(v0.z), __float2bfloat16(v0.w));
        o.h[2] = __nv_bfloat162(__float2bfloat16(v1.x), __float2bfloat16(v1.y));
        o.h[3] = __nv_bfloat162(__float2bfloat16(v1.z), __float2bfloat16(v1.w));
        ((uint4*)Y)[i] = o.u;
    }
}

template <int PAT>
__global__ void __launch_bounds__(256)
cvt_split3(const float* __restrict__ X, __nv_bfloat16* __restrict__ Y, size_t n8)
{
    size_t i = (size_t)blockIdx.x * blockDim.x + threadIdx.x;
    const size_t stride = (size_t)gridDim.x * blockDim.x;
    for (; i < n8; i += stride) {
        const float4* src = (const float4*)X + i * 2;
        float4 v0 = src[0], v1 = src[1];
        float f[8] = {v0.x, v0.y, v0.z, v0.w, v1.x, v1.y, v1.z, v1.w};
        union { __nv_bfloat16 h[24]; uint4 u[3]; } o;
#pragma unroll
        for (int j = 0; j < 8; j++) {
            __nv_bfloat16 hi = __float2bfloat16(f[j]);
            __nv_bfloat16 lo = __float2bfloat16(f[j] - __bfloat162float(hi));
            if (PAT == 0) { o.h[3*j] = hi; o.h[3*j+1] = lo; o.h[3*j+2] = hi; }
            else          { o.h[3*j] = hi; o.h[3*j+1] = hi; o.h[3*j+2] = lo; }
        }
        uint4* dst = (uint4*)(Y + i * 24);
        dst[0] = o.u[0]; dst[1] = o.u[1]; dst[2] = o.u[2];
    }
}

__global__ void zero_f32(float* __restrict__ p, int n)
{
    int i = blockIdx.x * blockDim.x + threadIdx.x;
    if (i < n) p[i] = 0.f;
}

// ---------------------------------------------------------------------------
// 128x128 HMMA core
// ---------------------------------------------------------------------------
#define BMg 128
#define BKg 32
#define STG 3
#define ROWB  80
#define TILEB (BMg * ROWB)
#define STAGEB (2 * TILEB)

#define MMA_CORE_LOOP(A_, B_, Kdim_, Mbound_)                                         \
    const int lrow = tid >> 1;                                                        \
    const int lc   = (tid & 1) * 2;                                                   \
    auto load_stage = [&](int s, int k0) {                                            \
        const uint32_t sa = base + (uint32_t)s * STAGEB;                              \
        const uint32_t sb = sa + TILEB;                                               \
        const __nv_bfloat16* ga = A_ + (size_t)(m0 + lrow) * Kdim_ + k0 + lc * 8;     \
        const int pa = (m0 + lrow) < Mbound_ ? 16 : 0;                                \
        cp16(sa + lrow * ROWB + lc * 16,       ga,     pa);                           \
        cp16(sa + lrow * ROWB + (lc + 1) * 16, ga + 8, pa);                           \
        const __nv_bfloat16* gb = B_ + (size_t)(n0 + lrow) * Kdim_ + k0 + lc * 8;     \
        cp16(sb + lrow * ROWB + lc * 16,       gb,     16);                           \
        cp16(sb + lrow * ROWB + (lc + 1) * 16, gb + 8, 16);                           \
    };                                                                                \
    const int niter = Kdim_ / BKg;                                                    \
    _Pragma("unroll")                                                                 \
    for (int s = 0; s < STG - 1; s++) {                                               \
        load_stage(s, s * BKg);                                                       \
        asm volatile("cp.async.commit_group;" ::: "memory");                          \
    }                                                                                 \
    for (int it = 0; it < niter; it++) {                                              \
        asm volatile("cp.async.wait_group %0;" :: "n"(STG - 2) : "memory");           \
        __syncthreads();                                                              \
        const int pf = it + STG - 1;                                                  \
        if (pf < niter) load_stage(pf % STG, pf * BKg);                               \
        asm volatile("cp.async.commit_group;" ::: "memory");                          \
        const uint32_t sa = base + (uint32_t)(it % STG) * STAGEB;                     \
        const uint32_t sb = sa + TILEB;                                               \
        _Pragma("unroll")                                                             \
        for (int h = 0; h < 2; h++) {                                                 \
            uint32_t a[2][4], b4[4][4];                                               \
            const int koff = (h * 16 + ((lane >> 4) * 8)) * 2;                        \
            _Pragma("unroll")                                                         \
            for (int mf = 0; mf < 2; mf++) {                                          \
                uint32_t addr = sa + (wm * 32 + mf * 16 + (lane & 15)) * ROWB + koff; \
                asm volatile("ldmatrix.sync.aligned.m8n8.x4.shared.b16 {%0,%1,%2,%3}, [%4];" \
                             : "=r"(a[mf][0]), "=r"(a[mf][1]), "=r"(a[mf][2]), "=r"(a[mf][3]) \
                             : "r"(addr));                                            \
            }                                                                         \
            _Pragma("unroll")                                                         \
            for (int nb = 0; nb < 4; nb++) {                                          \
                uint32_t addr = sb + (wn * 64 + nb * 16 + (lane & 15)) * ROWB + koff; \
                asm volatile("ldmatrix.sync.aligned.m8n8.x4.shared.b16 {%0,%1,%2,%3}, [%4];" \
                             : "=r"(b4[nb][0]), "=r"(b4[nb][1]), "=r"(b4[nb][2]), "=r"(b4[nb][3]) \
                             : "r"(addr));                                            \
            }                                                                         \
            _Pragma("unroll")                                                         \
            for (int mf = 0; mf < 2; mf++) {                                          \
                _Pragma("unroll")                                                     \
                for (int nf = 0; nf < 8; nf++) {                                      \
                    const uint32_t bb0 = (nf & 1) ? b4[nf >> 1][1] : b4[nf >> 1][0];  \
                    const uint32_t bb1 = (nf & 1) ? b4[nf >> 1][3] : b4[nf >> 1][2];  \
                    asm volatile(                                                     \
                        "mma.sync.aligned.m16n8k16.row.col.f32.bf16.bf16.f32 "        \
                        "{%0,%1,%2,%3}, {%4,%5,%6,%7}, {%8,%9}, {%0,%1,%2,%3};"       \
                        : "+f"(acc[mf][nf][0]), "+f"(acc[mf][nf][1]),                 \
                          "+f"(acc[mf][nf][2]), "+f"(acc[mf][nf][3])                  \
                        : "r"(a[mf][0]), "r"(a[mf][1]), "r"(a[mf][2]), "r"(a[mf][3]), \
                          "r"(bb0), "r"(bb1));                                        \
                }                                                                     \
            }                                                                         \
        }                                                                             \
    }                                                                                 \
    asm volatile("cp.async.wait_group 0;" ::: "memory");

// ---------------------------------------------------------------------------
// Logits GEMM with FUSED softmax epilogue -> writes P3 split-3 directly.
// Full z=6 grid, single launch (round-11 schedule position).
// ---------------------------------------------------------------------------
__global__ void __launch_bounds__(256, 2)
mma_logits_sm(const __nv_bfloat16* __restrict__ X3, const __nv_bfloat16* __restrict__ U3,
              const float* __restrict__ CB, const float* __restrict__ SS,
              __nv_bfloat16* __restrict__ P3)
{
    extern __shared__ char ds[];
    const uint32_t base = smem_u32(ds);
    const int tid  = threadIdx.x;
    const int lane = tid & 31;
    const int warp = tid >> 5;
    const int wm   = warp & 3;
    const int wn   = warp >> 2;
    const int blk  = blockIdx.z;
    const int m0 = blockIdx.y * BMg, n0 = blockIdx.x * BMg;

    const __nv_bfloat16* A = X3 + (size_t)blk * HWQ * K2;
    const __nv_bfloat16* B = U3 + (size_t)blk * NCOLS * K2;
    const float* bias = CB + blk * NCOLS;

    float acc[2][8][4];
#pragma unroll
    for (int a = 0; a < 2; a++)
#pragma unroll
        for (int b = 0; b < 8; b++)
#pragma unroll
            for (int c = 0; c < 4; c++) acc[a][b][c] = 0.f;

    MMA_CORE_LOOP(A, B, K2, HWQ)

    // fused softmax epilogue (per-head 16-logit softmax = quad reduction)
#pragma unroll
    for (int mf = 0; mf < 2; mf++) {
        const int r0 = m0 + wm * 32 + mf * 16 + (lane >> 2);
        const int r1 = r0 + 8;
        const bool ok0 = r0 < HWQ, ok1 = r1 < HWQ;
        const float sc0 = ok0 ? rsqrtf(__ldg(&SS[blk * HWQ + r0]) * (1.0f / DIMV) + 1e-6f)
                                * 0.08838834764831845f : 0.f;
        const float sc1 = ok1 ? rsqrtf(__ldg(&SS[blk * HWQ + r1]) * (1.0f / DIMV) + 1e-6f)
                                * 0.08838834764831845f : 0.f;
#pragma unroll
        for (int q = 0; q < 4; q++) {
            const int cA = n0 + wn * 64 + (2 * q) * 8 + (lane & 3) * 2;
            const int cB = cA + 8;
            const float cb0 = __ldg(&bias[cA]), cb1 = __ldg(&bias[cA + 1]);
            const float cb2 = __ldg(&bias[cB]), cb3 = __ldg(&bias[cB + 1]);
            float l0[4] = { (acc[mf][2*q][0] + cb0) * sc0, (acc[mf][2*q][1] + cb1) * sc0,
                            (acc[mf][2*q+1][0] + cb2) * sc0, (acc[mf][2*q+1][1] + cb3) * sc0 };
            float l1[4] = { (acc[mf][2*q][2] + cb0) * sc1, (acc[mf][2*q][3] + cb1) * sc1,
                            (acc[mf][2*q+1][2] + cb2) * sc1, (acc[mf][2*q+1][3] + cb3) * sc1 };
            float mx0 = fmaxf(fmaxf(l0[0], l0[1]), fmaxf(l0[2], l0[3]));
            float mx1 = fmaxf(fmaxf(l1[0], l1[1]), fmaxf(l1[2], l1[3]));
            mx0 = fmaxf(mx0, __shfl_xor_sync(~0u, mx0, 1));
            mx0 = fmaxf(mx0, __shfl_xor_sync(~0u, mx0, 2));
            mx1 = fmaxf(mx1, __shfl_xor_sync(~0u, mx1, 1));
            mx1 = fmaxf(mx1, __shfl_xor_sync(~0u, mx1, 2));
            float s0 = 0.f, s1 = 0.f;
#pragma unroll
            for (int j = 0; j < 4; j++) { l0[j] = __expf(l0[j] - mx0); s0 += l0[j]; }
#pragma unroll
            for (int j = 0; j < 4; j++) { l1[j] = __expf(l1[j] - mx1); s1 += l1[j]; }
            s0 += __shfl_xor_sync(~0u, s0, 1); s0 += __shfl_xor_sync(~0u, s0, 2);
            s1 += __shfl_xor_sync(~0u, s1, 1); s1 += __shfl_xor_sync(~0u, s1, 2);
            const float i0 = 1.f / s0, i1 = 1.f / s1;
            if (ok0) {
                __nv_bfloat16* d = P3 + (size_t)(blk * HWQ + r0) * K3P;
                st_p3pair(d + 3 * cA, l0[0] * i0, l0[1] * i0);
                st_p3pair(d + 3 * cB, l0[2] * i0, l0[3] * i0);
            }
            if (ok1) {
                __nv_bfloat16* d = P3 + (size_t)(blk * HWQ + r1) * K3P;
                st_p3pair(d + 3 * cA, l1[0] * i1, l1[1] * i1);
                st_p3pair(d + 3 * cB, l1[2] * i1, l1[3] * i1);
            }
        }
    }
}

// ---------------------------------------------------------------------------
// 128x256 HMMA core (norm GEMM, P@VT)
// ---------------------------------------------------------------------------
#define A2B    10240
#define STAGE2B 30720
#define STG2   3

#define MMA256_CORE(A_, B_, Kdim_, Mbound_)                                           \
    auto load_stage = [&](int s, int k0) {                                            \
        const uint32_t sa = base + (uint32_t)s * STAGE2B;                             \
        const uint32_t sb = sa + A2B;                                                 \
        _Pragma("unroll")                                                             \
        for (int it2 = 0; it2 < 6; it2++) {                                           \
            int idx = tid + 256 * it2;                                                \
            int row = idx >> 2, c = idx & 3;                                          \
            if (row < 128) {                                                          \
                const __nv_bfloat16* g = A_ + (size_t)(m0 + row) * Kdim_ + k0 + c * 8;\
                cp16(sa + row * 80 + c * 16, g, (m0 + row) < Mbound_ ? 16 : 0);       \
            } else {                                                                  \
                int br = row - 128;                                                   \
                const __nv_bfloat16* g = B_ + (size_t)(n0 + br) * Kdim_ + k0 + c * 8; \
                cp16(sb + br * 80 + c * 16, g, 16);                                   \
            }                                                                         \
        }                                                                             \
    };                                                                                \
    const int niter = Kdim_ / 32;                                                     \
    _Pragma("unroll")                                                                 \
    for (int s = 0; s < STG2 - 1; s++) {                                              \
        load_stage(s, s * 32);                                                        \
        asm volatile("cp.async.commit_group;" ::: "memory");                          \
    }                                                                                 \
    for (int it = 0; it < niter; it++) {                                              \
        asm volatile("cp.async.wait_group %0;" :: "n"(STG2 - 2) : "memory");          \
        __syncthreads();                                                              \
        const int pf = it + STG2 - 1;                                                 \
        if (pf < niter) load_stage(pf % STG2, pf * 32);                               \
        asm volatile("cp.async.commit_group;" ::: "memory");                          \
        const uint32_t sa = base + (uint32_t)(it % STG2) * STAGE2B;                   \
        const uint32_t sb = sa + A2B;                                                 \
        _Pragma("unroll")                                                             \
        for (int h = 0; h < 2; h++) {                                                 \
            uint32_t a4[4][4], b4[4][4];                                              \
            const int koff = (h * 16 + ((lane >> 4) * 8)) * 2;                        \
            _Pragma("unroll")                                                         \
            for (int mf = 0; mf < 4; mf++) {                                          \
                uint32_t addr = sa + (wm * 64 + mf * 16 + (lane & 15)) * 80 + koff;   \
                asm volatile("ldmatrix.sync.aligned.m8n8.x4.shared.b16 {%0,%1,%2,%3}, [%4];" \
                             : "=r"(a4[mf][0]), "=r"(a4[mf][1]), "=r"(a4[mf][2]), "=r"(a4[mf][3]) \
                             : "r"(addr));                                            \
            }                                                                         \
            _Pragma("unroll")                                                         \
            for (int nb = 0; nb < 4; nb++) {                                          \
                uint32_t addr = sb + (wn * 64 + nb * 16 + (lane & 15)) * 80 + koff;   \
                asm volatile("ldmatrix.sync.aligned.m8n8.x4.shared.b16 {%0,%1,%2,%3}, [%4];" \
                             : "=r"(b4[nb][0]), "=r"(b4[nb][1]), "=r"(b4[nb][2]), "=r"(b4[nb][3]) \
                             : "r"(addr));                                            \
            }                                                                         \
            _Pragma("unroll")                                                         \
            for (int mf = 0; mf < 4; mf++) {                                          \
                _Pragma("unroll")                                                     \
                for (int nf = 0; nf < 8; nf++) {                                      \
                    const uint32_t bb0 = (nf & 1) ? b4[nf >> 1][1] : b4[nf >> 1][0];  \
                    const uint32_t bb1 = (nf & 1) ? b4[nf >> 1][3] : b4[nf >> 1][2];  \
                    asm volatile(                                                     \
                        "mma.sync.aligned.m16n8k16.row.col.f32.bf16.bf16.f32 "        \
                        "{%0,%1,%2,%3}, {%4,%5,%6,%7}, {%8,%9}, {%0,%1,%2,%3};"       \
                        : "+f"(acc[mf][nf][0]), "+f"(acc[mf][nf][1]),                 \
                          "+f"(acc[mf][nf][2]), "+f"(acc[mf][nf][3])                  \
                        : "r"(a4[mf][0]), "r"(a4[mf][1]), "r"(a4[mf][2]), "r"(a4[mf][3]), \
                          "r"(bb0), "r"(bb1));                                        \
                }                                                                     \
            }                                                                         \
        }                                                                             \
    }                                                                                 \
    asm volatile("cp.async.wait_group 0;" ::: "memory");

__global__ void __launch_bounds__(256, 1)
mma256_ss(const __nv_bfloat16* __restrict__ A, const __nv_bfloat16* __restrict__ B,
          const float* __restrict__ bias, float* __restrict__ SS,
          int M, int N, int K)
{
    extern __shared__ char ds[];
    const uint32_t base = smem_u32(ds);
    const int tid  = threadIdx.x;
    const int lane = tid & 31;
    const int warp = tid >> 5;
    const int wm   = warp & 1;
    const int wn   = warp >> 1;
    const int m0 = blockIdx.y * 128, n0 = blockIdx.x * 256;

    float acc[4][8][4];
#pragma unroll
    for (int a = 0; a < 4; a++)
#pragma unroll
        for (int b = 0; b < 8; b++)
#pragma unroll
            for (int c = 0; c < 4; c++) acc[a][b][c] = 0.f;

    MMA256_CORE(A, B, K, M)

#pragma unroll
    for (int mf = 0; mf < 4; mf++) {
        const int r0 = m0 + wm * 64 + mf * 16 + (lane >> 2);
        float s0 = 0.f, s1 = 0.f;
#pragma unroll
        for (int nf = 0; nf < 8; nf++) {
            const int col = n0 + wn * 64 + nf * 8 + (lane & 3) * 2;
            const float b0 = __ldg(&bias[col]), b1 = __ldg(&bias[col + 1]);
            float v0 = acc[mf][nf][0] + b0, v1 = acc[mf][nf][1] + b1;
            float v2 = acc[mf][nf][2] + b0, v3 = acc[mf][nf][3] + b1;
            s0 += v0 * v0 + v1 * v1;
            s1 += v2 * v2 + v3 * v3;
        }
        s0 += __shfl_xor_sync(~0u, s0, 1); s0 += __shfl_xor_sync(~0u, s0, 2);
        s1 += __shfl_xor_sync(~0u, s1, 1); s1 += __shfl_xor_sync(~0u, s1, 2);
        if ((lane & 3) == 0) {
            if (r0 < M)     atomicAdd(&SS[r0], s0);
            if (r0 + 8 < M) atomicAdd(&SS[r0 + 8], s1);
        }
    }
}

__global__ void __launch_bounds__(256, 1)
mma256_z(const __nv_bfloat16* __restrict__ Ab, const __nv_bfloat16* __restrict__ Bb,
         const float* __restrict__ bias, float* __restrict__ Cb,
         int M, int N, int K, size_t sA, size_t sB, size_t sC)
{
    extern __shared__ char ds[];
    const uint32_t base = smem_u32(ds);
    const int tid  = threadIdx.x;
    const int lane = tid & 31;
    const int warp = tid >> 5;
    const int wm   = warp & 1;
    const int wn   = warp >> 1;
    const int blk  = blockIdx.z;
    const int m0 = blockIdx.y * 128, n0 = blockIdx.x * 256;

    const __nv_bfloat16* A = Ab + (size_t)blk * sA;
    const __nv_bfloat16* B = Bb + (size_t)blk * sB;
    float* C = Cb + (size_t)blk * sC;

    float acc[4][8][4];
#pragma unroll
    for (int a = 0; a < 4; a++)
#pragma unroll
        for (int b = 0; b < 8; b++)
#pragma unroll
            for (int c = 0; c < 4; c++) acc[a][b][c] = 0.f;

    MMA256_CORE(A, B, K, M)

#pragma unroll
    for (int mf = 0; mf < 4; mf++) {
        const int r0 = m0 + wm * 64 + mf * 16 + (lane >> 2);
#pragma unroll
        for (int nf = 0; nf < 8; nf++) {
            const int col = n0 + wn * 64 + nf * 8 + (lane & 3) * 2;
            const float b0 = __ldg(&bias[col]), b1 = __ldg(&bias[col + 1]);
            if (r0 < M) {
                float2 v = make_float2(acc[mf][nf][0] + b0, acc[mf][nf][1] + b1);
                *(float2*)(C + (size_t)r0 * N + col) = v;
            }
            if (r0 + 8 < M) {
                float2 v = make_float2(acc[mf][nf][2] + b0, acc[mf][nf][3] + b1);
                *(float2*)(C + (size_t)(r0 + 8) * N + col) = v;
            }
        }
    }
}

// ---------------------------------------------------------------------------
// SIMT fp32 GEMM for KV projections (z-merged)
// ---------------------------------------------------------------------------
__global__ void __launch_bounds__(256, 2)
gemm_kv(const float* __restrict__ A,
        const float* __restrict__ Wk, const float* __restrict__ bk, float* __restrict__ Ck,
        const float* __restrict__ Wv, const float* __restrict__ bv, float* __restrict__ Cv,
        int M, int N, int K)
{
    const float* B    = blockIdx.z ? Wv : Wk;
    const float* bias = blockIdx.z ? bv : bk;
    float* C          = blockIdx.z ? Cv : Ck;

    const int BM = 128, BN = 128, BK = 16;
    __shared__ float As[BK][BM + 4];
    __shared__ float Bs[BK][BN + 4];

    const int tid  = threadIdx.x;
    const int tx   = tid & 15;
    const int ty   = tid >> 4;
    const int col0 = blockIdx.x * BN;

    float acc[8][8];
#pragma unroll
    for (int i = 0; i < 8; i++)
#pragma unroll
        for (int j = 0; j < 8; j++) acc[i][j] = 0.f;

    for (int k0 = 0; k0 < K; k0 += BK) {
#pragma unroll
        for (int it = 0; it < 2; it++) {
            int i = tid + 256 * it;
            int r = i >> 2, c4 = i & 3;
            float4 v = make_float4(0.f, 0.f, 0.f, 0.f);
            if (r < M) v = *(const float4*)(A + (size_t)r * K + k0 + c4 * 4);
            As[c4 * 4 + 0][r] = v.x; As[c4 * 4 + 1][r] = v.y;
            As[c4 * 4 + 2][r] = v.z; As[c4 * 4 + 3][r] = v.w;
        }
#pragma unroll
        for (int it = 0; it < 2; it++) {
            int i = tid + 256 * it;
            int r = i >> 2, c4 = i & 3;
            float4 v = *(const float4*)(B + (size_t)(col0 + r) * K + k0 + c4 * 4);
            Bs[c4 * 4 + 0][r] = v.x; Bs[c4 * 4 + 1][r] = v.y;
            Bs[c4 * 4 + 2][r] = v.z; Bs[c4 * 4 + 3][r] = v.w;
        }
        __syncthreads();
#pragma unroll
        for (int kk = 0; kk < BK; kk++) {
            float a[8], b[8];
#pragma unroll
            for (int i = 0; i < 8; i++) a[i] = As[kk][ty * 8 + i];
#pragma unroll
            for (int j = 0; j < 8; j++) b[j] = Bs[kk][tx * 8 + j];
#pragma unroll
            for (int i = 0; i < 8; i++)
#pragma unroll
                for (int j = 0; j < 8; j++)
                    acc[i][j] = fmaf(a[i], b[j], acc[i][j]);
        }
        __syncthreads();
    }
#pragma unroll
    for (int i = 0; i < 8; i++) {
        int r = ty * 8 + i;
        if (r >= M) continue;
#pragma unroll
        for (int j4 = 0; j4 < 2; j4++) {
            int c = col0 + tx * 8 + j4 * 4;
            float4 o;
            o.x = acc[i][j4 * 4 + 0] + bias[c + 0];
            o.y = acc[i][j4 * 4 + 1] + bias[c + 1];
            o.z = acc[i][j4 * 4 + 2] + bias[c + 2];
            o.w = acc[i][j4 * 4 + 3] + bias[c + 3];
            *(float4*)(C + (size_t)r * N + c) = o;
        }
    }
}

// ---------------------------------------------------------------------------
// VTg[blk][n][h*16+j] = sum_d v[blk*16+j, h*128+d] * Wo[n, h*128+d]
// ---------------------------------------------------------------------------
__global__ void __launch_bounds__(256, 2)
vproj_kernel(const float* __restrict__ V, const float* __restrict__ Wo,
             float* __restrict__ VTg)
{
    const int h  = blockIdx.y;
    const int n0 = blockIdx.x * 128;
    const int tid = threadIdx.x;
    const int tx = tid & 15;
    const int ty = tid >> 4;

    __shared__ float As[16][96 + 4];
    __shared__ float Bs[16][128 + 4];

    float acc[6][8];
#pragma unroll
    for (int i = 0; i < 6; i++)
#pragma unroll
        for (int j = 0; j < 8; j++) acc[i][j] = 0.f;

    for (int kc = 0; kc < 8; kc++) {
        const int kbase = h * HD + kc * 16;
#pragma unroll
        for (int it = 0; it < 2; it++) {
            int i = tid + 256 * it;
            if (i < 384) {
                int r = i >> 2, c4 = i & 3;
                float4 v = *(const float4*)(V + (size_t)r * DIMV + kbase + c4 * 4);
                As[c4 * 4 + 0][r] = v.x; As[c4 * 4 + 1][r] = v.y;
                As[c4 * 4 + 2][r] = v.z; As[c4 * 4 + 3][r] = v.w;
            }
        }
#pragma unroll
        for (int it = 0; it < 2; it++) {
            int i = tid + 256 * it;
            int r = i >> 2, c4 = i & 3;
            float4 v = *(const float4*)(Wo + (size_t)(n0 + r) * DIMV + kbase + c4 * 4);
            Bs[c4 * 4 + 0][r] = v.x; Bs[c4 * 4 + 1][r] = v.y;
            Bs[c4 * 4 + 2][r] = v.z; Bs[c4 * 4 + 3][r] = v.w;
        }
        __syncthreads();
#pragma unroll
        for (int kk = 0; kk < 16; kk++) {
            float a[6], b[8];
#pragma unroll
            for (int i = 0; i < 6; i++) a[i] = As[kk][ty * 6 + i];
#pragma unroll
            for (int j = 0; j < 8; j++) b[j] = Bs[kk][tx * 8 + j];
#pragma unroll
            for (int i = 0; i < 6; i++)
#pragma unroll
                for (int j = 0; j < 8; j++)
                    acc[i][j] = fmaf(a[i], b[j], acc[i][j]);
        }
        __syncthreads();
    }

#pragma unroll
    for (int i = 0; i < 6; i++) {
        const int jg = ty * 6 + i;
        float* dst = VTg + (size_t)(jg >> 4) * DIMV * NCOLS + h * NKV + (jg & 15);
#pragma unroll
        for (int j = 0; j < 8; j++)
            dst[(size_t)(n0 + tx * 8 + j) * NCOLS] = acc[i][j];
    }
}

// ---------------------------------------------------------------------------
// uproj: emits U3 split-3 (hi,hi,lo) directly, coalesced 48B uint4 stores.
// ---------------------------------------------------------------------------
__global__ void __launch_bounds__(256, 2)
uproj_kernel(const float* __restrict__ Kn, const float* __restrict__ Wq,
             const float* __restrict__ gq, __nv_bfloat16* __restrict__ U3)
{
    const int h  = blockIdx.y;
    const int m0 = blockIdx.x * 128;
    const int tid = threadIdx.x;
    const int tx = tid & 15;
    const int ty = tid >> 4;

    __shared__ float As[16][96 + 4];
    __shared__ float Bs[16][128 + 4];

    float acc[6][8];
#pragma unroll
    for (int i = 0; i < 6; i++)
#pragma unroll
        for (int j = 0; j < 8; j++) acc[i][j] = 0.f;

    for (int kc = 0; kc < 8; kc++) {
        const int kbase = h * HD + kc * 16;
#pragma unroll
        for (int it = 0; it < 2; it++) {
            int i = tid + 256 * it;
            if (i < 384) {
                int r = i >> 2, c4 = i & 3;
                float4 v = *(const float4*)(Kn + (size_t)r * DIMV + kbase + c4 * 4);
                float4 g = *(const float4*)(gq + kbase + c4 * 4);
                As[c4 * 4 + 0][r] = v.x * g.x; As[c4 * 4 + 1][r] = v.y * g.y;
                As[c4 * 4 + 2][r] = v.z * g.z; As[c4 * 4 + 3][r] = v.w * g.w;
            }
        }
#pragma unroll
        for (int it = 0; it < 2; it++) {
            int i = tid + 256 * it;
            int kr = i >> 5, c4 = i & 31;
            float4 v = *(const float4*)(Wq + (size_t)(kbase + kr) * DIMV + m0 + c4 * 4);
            Bs[kr][c4 * 4 + 0] = v.x; Bs[kr][c4 * 4 + 1] = v.y;
            Bs[kr][c4 * 4 + 2] = v.z; Bs[kr][c4 * 4 + 3] = v.w;
        }
        __syncthreads();
#pragma unroll
        for (int kk = 0; kk < 16; kk++) {
            float a[6], b[8];
#pragma unroll
            for (int i = 0; i < 6; i++) a[i] = As[kk][ty * 6 + i];
#pragma unroll
            for (int j = 0; j < 8; j++) b[j] = Bs[kk][tx * 8 + j];
#pragma unroll
            for (int i = 0; i < 6; i++)
#pragma unroll
                for (int j = 0; j < 8; j++)
                    acc[i][j] = fmaf(a[i], b[j], acc[i][j]);
        }
        __syncthreads();
    }

#pragma unroll
    for (int i = 0; i < 6; i++) {
        const int jg  = ty * 6 + i;
        const int row = (jg >> 4) * NCOLS + h * NKV + (jg & 15);
        union { __nv_bfloat16 hh[24]; uint4 u[3]; } o;
#pragma unroll
        for (int j = 0; j < 8; j++) {
            float f = acc[i][j];
            __nv_bfloat16 hi = __float2bfloat16(f);
            __nv_bfloat16 lo = __float2bfloat16(f - __bfloat162float(hi));
            o.hh[3*j] = hi; o.hh[3*j+1] = hi; o.hh[3*j+2] = lo;
        }
        uint4* dst = (uint4*)(U3 + (size_t)row * K2 + 3 * (m0 + tx * 8));
        dst[0] = o.u[0]; dst[1] = o.u[1]; dst[2] = o.u[2];
    }
}

__global__ void __launch_bounds__(256)
cb_kernel(const float* __restrict__ Kn, const float* __restrict__ bq,
          const float* __restrict__ gq, float* __restrict__ CB)
{
    int col = blockIdx.x * blockDim.x + threadIdx.x;
    if (col >= NUALL) return;
    int blk = col / NCOLS, rem = col % NCOLS;
    int h = rem >> 4, j = rem & 15;
    int jg = blk * NKV + j;
    const float* kp = Kn + (size_t)jg * DIMV + h * HD;
    const float* bp = bq + h * HD;
    const float* gp = gq + h * HD;
    float s = 0.f;
#pragma unroll 4
    for (int d = 0; d < HD; d++) s = fmaf(bp[d] * gp[d], kp[d], s);
    CB[col] = s;
}

// ---------------------------------------------------------------------------
// rmsnorm (in-place) — K only
// ---------------------------------------------------------------------------
__global__ void __launch_bounds__(256)
rmsnorm_rows(float* __restrict__ X, const float* __restrict__ g)
{
    const int row = blockIdx.x;
    float* x = X + (size_t)row * DIMV;

    float ss = 0.f;
    for (int i = threadIdx.x; i < DIMV / 4; i += 256) {
        float4 v = ((const float4*)x)[i];
        ss += v.x * v.x + v.y * v.y + v.z * v.z + v.w * v.w;
    }
#pragma unroll
    for (int o = 16; o > 0; o >>= 1) ss += __shfl_xor_sync(~0u, ss, o);
    __shared__ float red[8];
    if ((threadIdx.x & 31) == 0) red[threadIdx.x >> 5] = ss;
    __syncthreads();
    if (threadIdx.x < 8) {
        float v = red[threadIdx.x];
#pragma unroll
        for (int o = 4; o > 0; o >>= 1) v += __shfl_xor_sync(0xffu, v, o);
        if (threadIdx.x == 0) red[0] = v;
    }
    __syncthreads();
    const float scale = rsqrtf(red[0] * (1.0f / DIMV) + 1e-6f);

    for (int i = threadIdx.x; i < DIMV / 4; i += 256) {
        float4 v  = ((const float4*)x)[i];
        float4 gg = ((const float4*)g)[i];
        v.x *= scale * gg.x; v.y *= scale * gg.y;
        v.z *= scale * gg.z; v.w *= scale * gg.w;
        ((float4*)x)[i] = v;
    }
}

// ---------------------------------------------------------------------------
// launch — round-11 schedule; ONLY change: logits+softmax fused, single launch
// ---------------------------------------------------------------------------
extern "C" void kernel_launch(void* const* d_in, const int* in_sizes, int n_in,
                              void* d_out, int out_size)
{
    (void)in_sizes; (void)n_in; (void)out_size;
    const float* x   = (const float*)d_in[0];
    const float* ctx = (const float*)d_in[1];
    const float* Wq = (const float*)d_in[6];
    const float* bq = (const float*)d_in[7];
    const float* Wk = (const float*)d_in[8];
    const float* bk = (const float*)d_in[9];
    const float* Wv = (const float*)d_in[10];
    const float* bv = (const float*)d_in[11];
    const float* Wo = (const float*)d_in[12];
    const float* bo = (const float*)d_in[13];
    const float* gq = (const float*)d_in[14];
    const float* gk = (const float*)d_in[15];
    float* out = (float*)d_out;

    float *kb, *vb, *vtg, *cb, *ssb;
    __nv_bfloat16 *xb, *wb, *x3, *u3, *p3, *vt3;
    cudaGetSymbolAddress((void**)&kb,  g_k);
    cudaGetSymbolAddress((void**)&vb,  g_v);
    cudaGetSymbolAddress((void**)&vtg, g_vtg);
    cudaGetSymbolAddress((void**)&cb,  g_cb);
    cudaGetSymbolAddress((void**)&ssb, g_ss);
    cudaGetSymbolAddress((void**)&xb,  g_xb);
    cudaGetSymbolAddress((void**)&wb,  g_wb);
    cudaGetSymbolAddress((void**)&x3,  g_x3);
    cudaGetSymbolAddress((void**)&u3,  g_u3);
    cudaGetSymbolAddress((void**)&p3,  g_p3);
    cudaGetSymbolAddress((void**)&vt3, g_vt3);

    const int dynsmem  = STG * STAGEB;
    const int dynsmem2 = STG2 * STAGE2B;

    static cudaStream_t sB = nullptr;
    static cudaEvent_t  e0 = nullptr, eW = nullptr, eB = nullptr;
    if (sB == nullptr) {
        cudaStreamCreateWithFlags(&sB, cudaStreamNonBlocking);
        cudaEventCreateWithFlags(&e0, cudaEventDisableTiming);
        cudaEventCreateWithFlags(&eW, cudaEventDisableTiming);
        cudaEventCreateWithFlags(&eB, cudaEventDisableTiming);
        cudaFuncSetAttribute(mma_logits_sm, cudaFuncAttributeMaxDynamicSharedMemorySize, dynsmem);
        cudaFuncSetAttribute(mma256_ss, cudaFuncAttributeMaxDynamicSharedMemorySize, dynsmem2);
        cudaFuncSetAttribute(mma256_z,  cudaFuncAttributeMaxDynamicSharedMemorySize, dynsmem2);
    }

    // fork
    cudaEventRecord(e0, 0);
    cudaStreamWaitEvent(sB, e0, 0);

    // side stream B: Wq->bf16 + ss zero first (norm GEMM waits on eW),
    // then the KV prep chain (uproj emits u3 directly).
    zero_f32<<<(L1V + 255) / 256, 256, 0, sB>>>(ssb, L1V);
    cvt_bf16<<<2048, 256, 0, sB>>>(Wq, wb, (size_t)DIMV * DIMV / 8);
    cudaEventRecord(eW, sB);
    {
        dim3 grid(DIMV / 128, 1, 2);
        gemm_kv<<<grid, 256, 0, sB>>>(ctx, Wk, bk, kb, Wv, bv, vb, LAV, DIMV, KVDIM);
    }
    rmsnorm_rows<<<LAV, 256, 0, sB>>>(kb, gk);
    {
        dim3 grid(DIMV / 128, NH);
        vproj_kernel<<<grid, 256, 0, sB>>>(vb, Wo, vtg);
        uproj_kernel<<<grid, 256, 0, sB>>>(kb, Wq, gq, u3);
    }
    cb_kernel<<<(NUALL + 255) / 256, 256, 0, sB>>>(kb, bq, gq, cb);
    cvt_split3<1><<<2048, 256, 0, sB>>>(vtg, vt3, (size_t)NBLK * DIMV * NCOLS / 8);
    cudaEventRecord(eB, sB);

    // main: x conversion + norm GEMM (side chain hides underneath)
    cvt_x_fused<<<2048, 256>>>(x, xb, x3, (size_t)L1V * DIMV / 8);
    cudaStreamWaitEvent(0, eW, 0);
    {
        dim3 grid(DIMV / 256, (L1V + 127) / 128);
        mma256_ss<<<grid, 256, dynsmem2>>>(xb, wb, bq, ssb, L1V, DIMV, DIMV);
    }

    // join, then fused logits+softmax -> P@VT
    cudaStreamWaitEvent(0, eB, 0);
    {
        dim3 grid(NCOLS / 128, (HWQ + 127) / 128, NBLK);
        mma_logits_sm<<<grid, 256, dynsmem>>>(x3, u3, cb, ssb, p3);
    }
    {
        dim3 grid(DIMV / 256, (HWQ + 127) / 128, NBLK);
        mma256_z<<<grid, 256, dynsmem2>>>(
            p3, vt3, bo, out, HWQ, DIMV, K3P,
            (size_t)HWQ * K3P, (size_t)DIMV * K3P, (size_t)HWQ * DIMV);
    }
}

// round 14
// speedup vs baseline: 1.5736x; 1.5736x over previous
#include <cuda_runtime.h>
#include <cuda_bf16.h>
#include <math.h>
#include <stdint.h>

#define DIMV   5120
#define KVDIM  1536
#define NH     40
#define HD     128
#define L1V    9360
#define LAV    96
#define NBLK   6
#define NKV    16
#define HWQ    1560
#define K2     (3 * DIMV)
#define NCOLS  (NH * NKV)
#define K3P    (3 * NCOLS)
#define NUALL  (NBLK * NCOLS)

// ---------------- scratch ----------------------------------------------------
__device__ float g_k[(size_t)LAV * DIMV];
__device__ float g_v[(size_t)LAV * DIMV];
__device__ float g_vtg[(size_t)NBLK * DIMV * NCOLS];
__device__ float g_cb[NUALL];
__device__ float g_ss[L1V];
__device__ float g_lg[(size_t)L1V * NCOLS];
__device__ __nv_bfloat16 g_xb[(size_t)L1V * DIMV];
__device__ __nv_bfloat16 g_wb[(size_t)DIMV * DIMV];
__device__ __nv_bfloat16 g_x3[(size_t)L1V * K2];
__device__ __nv_bfloat16 g_u3[(size_t)NUALL * K2];
__device__ __nv_bfloat16 g_p3[(size_t)L1V * K3P];
__device__ __nv_bfloat16 g_vt3[(size_t)NBLK * DIMV * K3P];

// ---------------- helpers ----------------------------------------------------
__device__ __forceinline__ uint32_t smem_u32(const void* p) {
    uint32_t a;
    asm("{ .reg .u64 t; cvta.to.shared.u64 t, %1; cvt.u32.u64 %0, t; }" : "=r"(a) : "l"(p));
    return a;
}
__device__ __forceinline__ void cp16(uint32_t dst, const void* src, int srcsize) {
    asm volatile("cp.async.cg.shared.global [%0], [%1], 16, %2;"
                 :: "r"(dst), "l"(src), "r"(srcsize) : "memory");
}

// ---------------------------------------------------------------------------
// converters
// ---------------------------------------------------------------------------
__global__ void __launch_bounds__(256)
cvt_x_fused(const float* __restrict__ X, __nv_bfloat16* __restrict__ XB,
            __nv_bfloat16* __restrict__ X3, size_t n8)
{
    size_t i = (size_t)blockIdx.x * blockDim.x + threadIdx.x;
    const size_t stride = (size_t)gridDim.x * blockDim.x;
    for (; i < n8; i += stride) {
        const float4* src = (const float4*)X + i * 2;
        float4 v0 = src[0], v1 = src[1];
        float f[8] = {v0.x, v0.y, v0.z, v0.w, v1.x, v1.y, v1.z, v1.w};
        union { __nv_bfloat16 h[8];  uint4 u; }    ob;
        union { __nv_bfloat16 h[24]; uint4 u[3]; } o3;
#pragma unroll
        for (int j = 0; j < 8; j++) {
            __nv_bfloat16 hi = __float2bfloat16(f[j]);
            __nv_bfloat16 lo = __float2bfloat16(f[j] - __bfloat162float(hi));
            ob.h[j] = hi;
            o3.h[3*j] = hi; o3.h[3*j+1] = lo; o3.h[3*j+2] = hi;
        }
        ((uint4*)XB)[i] = ob.u;
        uint4* dst = (uint4*)(X3 + i * 24);
        dst[0] = o3.u[0]; dst[1] = o3.u[1]; dst[2] = o3.u[2];
    }
}

__global__ void __launch_bounds__(256)
cvt_bf16(const float* __restrict__ X, __nv_bfloat16* __restrict__ Y, size_t n8)
{
    size_t i = (size_t)blockIdx.x * blockDim.x + threadIdx.x;
    const size_t stride = (size_t)gridDim.x * blockDim.x;
    for (; i < n8; i += stride) {
        const float4* src = (const float4*)X + i * 2;
        float4 v0 = src[0], v1 = src[1];
        union { __nv_bfloat162 h[4]; uint4 u; } o;
        o.h[0] = __nv_bfloat162(__float2bfloat16(v0.x), __float2bfloat16(v0.y));
        o.h[1] = __nv_bfloat162(__float2bfloat16(v0.z), __float2bfloat16(v0.w));
        o.h[2] = __nv_bfloat162(__float2bfloat16(v1.x), __float2bfloat16(v1.y));
        o.h[3] = __nv_bfloat162(__float2bfloat16(v1.z), __float2bfloat16(v1.w));
        ((uint4*)Y)[i] = o.u;
    }
}

template <int PAT>   // 0: (hi,lo,hi); 1: (hi,hi,lo)
__global__ void __launch_bounds__(256)
cvt_split3(const float* __restrict__ X, __nv_bfloat16* __restrict__ Y, size_t n8)
{
    size_t i = (size_t)blockIdx.x * blockDim.x + threadIdx.x;
    const size_t stride = (size_t)gridDim.x * blockDim.x;
    for (; i < n8; i += stride) {
        const float4* src = (const float4*)X + i * 2;
        float4 v0 = src[0], v1 = src[1];
        float f[8] = {v0.x, v0.y, v0.z, v0.w, v1.x, v1.y, v1.z, v1.w};
        union { __nv_bfloat16 h[24]; uint4 u[3]; } o;
#pragma unroll
        for (int j = 0; j < 8; j++) {
            __nv_bfloat16 hi = __float2bfloat16(f[j]);
            __nv_bfloat16 lo = __float2bfloat16(f[j] - __bfloat162float(hi));
            if (PAT == 0) { o.h[3*j] = hi; o.h[3*j+1] = lo; o.h[3*j+2] = hi; }
            else          { o.h[3*j] = hi; o.h[3*j+1] = hi; o.h[3*j+2] = lo; }
        }
        uint4* dst = (uint4*)(Y + i * 24);
        dst[0] = o.u[0]; dst[1] = o.u[1]; dst[2] = o.u[2];
    }
}

__global__ void zero_f32(float* __restrict__ p, int n)
{
    int i = blockIdx.x * blockDim.x + threadIdx.x;
    if (i < n) p[i] = 0.f;
}

// ---------------------------------------------------------------------------
// 128x128 HMMA core (logits GEMM)
// ---------------------------------------------------------------------------
#define BMg 128
#define BKg 32
#define STG 3
#define ROWB  80
#define TILEB (BMg * ROWB)
#define STAGEB (2 * TILEB)

#define MMA_CORE_LOOP(A_, B_, Kdim_, Mbound_)                                         \
    const int lrow = tid >> 1;                                                        \
    const int lc   = (tid & 1) * 2;                                                   \
    auto load_stage = [&](int s, int k0) {                                            \
        const uint32_t sa = base + (uint32_t)s * STAGEB;                              \
        const uint32_t sb = sa + TILEB;                                               \
        const __nv_bfloat16* ga = A_ + (size_t)(m0 + lrow) * Kdim_ + k0 + lc * 8;     \
        const int pa = (m0 + lrow) < Mbound_ ? 16 : 0;                                \
        cp16(sa + lrow * ROWB + lc * 16,       ga,     pa);                           \
        cp16(sa + lrow * ROWB + (lc + 1) * 16, ga + 8, pa);                           \
        const __nv_bfloat16* gb = B_ + (size_t)(n0 + lrow) * Kdim_ + k0 + lc * 8;     \
        cp16(sb + lrow * ROWB + lc * 16,       gb,     16);                           \
        cp16(sb + lrow * ROWB + (lc + 1) * 16, gb + 8, 16);                           \
    };                                                                                \
    const int niter = Kdim_ / BKg;                                                    \
    _Pragma("unroll")                                                                 \
    for (int s = 0; s < STG - 1; s++) {                                               \
        load_stage(s, s * BKg);                                                       \
        asm volatile("cp.async.commit_group;" ::: "memory");                          \
    }                                                                                 \
    for (int it = 0; it < niter; it++) {                                              \
        asm volatile("cp.async.wait_group %0;" :: "n"(STG - 2) : "memory");           \
        __syncthreads();                                                              \
        const int pf = it + STG - 1;                                                  \
        if (pf < niter) load_stage(pf % STG, pf * BKg);                               \
        asm volatile("cp.async.commit_group;" ::: "memory");                          \
        const uint32_t sa = base + (uint32_t)(it % STG) * STAGEB;                     \
        const uint32_t sb = sa + TILEB;                                               \
        _Pragma("unroll")                                                             \
        for (int h = 0; h < 2; h++) {                                                 \
            uint32_t a[2][4], b4[4][4];                                               \
            const int koff = (h * 16 + ((lane >> 4) * 8)) * 2;                        \
            _Pragma("unroll")                                                         \
            for (int mf = 0; mf < 2; mf++) {                                          \
                uint32_t addr = sa + (wm * 32 + mf * 16 + (lane & 15)) * ROWB + koff; \
                asm volatile("ldmatrix.sync.aligned.m8n8.x4.shared.b16 {%0,%1,%2,%3}, [%4];" \
                             : "=r"(a[mf][0]), "=r"(a[mf][1]), "=r"(a[mf][2]), "=r"(a[mf][3]) \
                             : "r"(addr));                                            \
            }                                                                         \
            _Pragma("unroll")                                                         \
            for (int nb = 0; nb < 4; nb++) {                                          \
                uint32_t addr = sb + (wn * 64 + nb * 16 + (lane & 15)) * ROWB + koff; \
                asm volatile("ldmatrix.sync.aligned.m8n8.x4.shared.b16 {%0,%1,%2,%3}, [%4];" \
                             : "=r"(b4[nb][0]), "=r"(b4[nb][1]), "=r"(b4[nb][2]), "=r"(b4[nb][3]) \
                             : "r"(addr));                                            \
            }                                                                         \
            _Pragma("unroll")                                                         \
            for (int mf = 0; mf < 2; mf++) {                                          \
                _Pragma("unroll")                                                     \
                for (int nf = 0; nf < 8; nf++) {                                      \
                    const uint32_t bb0 = (nf & 1) ? b4[nf >> 1][1] : b4[nf >> 1][0];  \
                    const uint32_t bb1 = (nf & 1) ? b4[nf >> 1][3] : b4[nf >> 1][2];  \
                    asm volatile(                                                     \
                        "mma.sync.aligned.m16n8k16.row.col.f32.bf16.bf16.f32 "        \
                        "{%0,%1,%2,%3}, {%4,%5,%6,%7}, {%8,%9}, {%0,%1,%2,%3};"       \
                        : "+f"(acc[mf][nf][0]), "+f"(acc[mf][nf][1]),                 \
                          "+f"(acc[mf][nf][2]), "+f"(acc[mf][nf][3])                  \
                        : "r"(a[mf][0]), "r"(a[mf][1]), "r"(a[mf][2]), "r"(a[mf][3]), \
                          "r"(bb0), "r"(bb1));                                        \
                }                                                                     \
            }                                                                         \
        }                                                                             \
    }                                                                                 \
    asm volatile("cp.async.wait_group 0;" ::: "memory");

__global__ void __launch_bounds__(256, 2)
mma_gemm_z(const __nv_bfloat16* __restrict__ Ab, const __nv_bfloat16* __restrict__ Bb,
           const float* __restrict__ biasb, float* __restrict__ Cb,
           int M, int N, int K,
           size_t sA, size_t sB, size_t sC, int sBias)
{
    extern __shared__ char ds[];
    const uint32_t base = smem_u32(ds);
    const int tid  = threadIdx.x;
    const int lane = tid & 31;
    const int warp = tid >> 5;
    const int wm   = warp & 3;
    const int wn   = warp >> 2;
    const int blk  = blockIdx.z;
    const int m0 = blockIdx.y * BMg, n0 = blockIdx.x * BMg;

    const __nv_bfloat16* A = Ab + (size_t)blk * sA;
    const __nv_bfloat16* B = Bb + (size_t)blk * sB;
    const float* bias = biasb + (size_t)blk * sBias;
    float* C = Cb + (size_t)blk * sC;

    float acc[2][8][4];
#pragma unroll
    for (int a = 0; a < 2; a++)
#pragma unroll
        for (int b = 0; b < 8; b++)
#pragma unroll
            for (int c = 0; c < 4; c++) acc[a][b][c] = 0.f;

    MMA_CORE_LOOP(A, B, K, M)

#pragma unroll
    for (int mf = 0; mf < 2; mf++) {
        const int r0 = m0 + wm * 32 + mf * 16 + (lane >> 2);
#pragma unroll
        for (int nf = 0; nf < 8; nf++) {
            const int col = n0 + wn * 64 + nf * 8 + (lane & 3) * 2;
            const float b0 = __ldg(&bias[col]), b1 = __ldg(&bias[col + 1]);
            if (r0 < M) {
                float2 v = make_float2(acc[mf][nf][0] + b0, acc[mf][nf][1] + b1);
                *(float2*)(C + (size_t)r0 * N + col) = v;
            }
            if (r0 + 8 < M) {
                float2 v = make_float2(acc[mf][nf][2] + b0, acc[mf][nf][3] + b1);
                *(float2*)(C + (size_t)(r0 + 8) * N + col) = v;
            }
        }
    }
}

// ---------------------------------------------------------------------------
// 128x256 HMMA core (norm GEMM, P@VT)
// ---------------------------------------------------------------------------
#define A2B    10240
#define STAGE2B 30720
#define STG2   3

#define MMA256_CORE(A_, B_, Kdim_, Mbound_)                                           \
    auto load_stage = [&](int s, int k0) {                                            \
        const uint32_t sa = base + (uint32_t)s * STAGE2B;                             \
        const uint32_t sb = sa + A2B;                                                 \
        _Pragma("unroll")                                                             \
        for (int it2 = 0; it2 < 6; it2++) {                                           \
            int idx = tid + 256 * it2;                                                \
            int row = idx >> 2, c = idx & 3;                                          \
            if (row < 128) {                                                          \
                const __nv_bfloat16* g = A_ + (size_t)(m0 + row) * Kdim_ + k0 + c * 8;\
                cp16(sa + row * 80 + c * 16, g, (m0 + row) < Mbound_ ? 16 : 0);       \
            } else {                                                                  \
                int br = row - 128;                                                   \
                const __nv_bfloat16* g = B_ + (size_t)(n0 + br) * Kdim_ + k0 + c * 8; \
                cp16(sb + br * 80 + c * 16, g, 16);                                   \
            }                                                                         \
        }                                                                             \
    };                                                                                \
    const int niter = Kdim_ / 32;                                                     \
    _Pragma("unroll")                                                                 \
    for (int s = 0; s < STG2 - 1; s++) {                                              \
        load_stage(s, s * 32);                                                        \
        asm volatile("cp.async.commit_group;" ::: "memory");                          \
    }                                                                                 \
    for (int it = 0; it < niter; it++) {                                              \
        asm volatile("cp.async.wait_group %0;" :: "n"(STG2 - 2) : "memory");          \
        __syncthreads();                                                              \
        const int pf = it + STG2 - 1;                                                 \
        if (pf < niter) load_stage(pf % STG2, pf * 32);                               \
        asm volatile("cp.async.commit_group;" ::: "memory");                          \
        const uint32_t sa = base + (uint32_t)(it % STG2) * STAGE2B;                   \
        const uint32_t sb = sa + A2B;                                                 \
        _Pragma("unroll")                                                             \
        for (int h = 0; h < 2; h++) {                                                 \
            uint32_t a4[4][4], b4[4][4];                                              \
            const int koff = (h * 16 + ((lane >> 4) * 8)) * 2;                        \
            _Pragma("unroll")                                                         \
            for (int mf = 0; mf < 4; mf++) {                                          \
                uint32_t addr = sa + (wm * 64 + mf * 16 + (lane & 15)) * 80 + koff;   \
                asm volatile("ldmatrix.sync.aligned.m8n8.x4.shared.b16 {%0,%1,%2,%3}, [%4];" \
                             : "=r"(a4[mf][0]), "=r"(a4[mf][1]), "=r"(a4[mf][2]), "=r"(a4[mf][3]) \
                             : "r"(addr));                                            \
            }                                                                         \
            _Pragma("unroll")                                                         \
            for (int nb = 0; nb < 4; nb++) {                                          \
                uint32_t addr = sb + (wn * 64 + nb * 16 + (lane & 15)) * 80 + koff;   \
                asm volatile("ldmatrix.sync.aligned.m8n8.x4.shared.b16 {%0,%1,%2,%3}, [%4];" \
                             : "=r"(b4[nb][0]), "=r"(b4[nb][1]), "=r"(b4[nb][2]), "=r"(b4[nb][3]) \
                             : "r"(addr));                                            \
            }                                                                         \
            _Pragma("unroll")                                                         \
            for (int mf = 0; mf < 4; mf++) {                                          \
                _Pragma("unroll")                                                     \
                for (int nf = 0; nf < 8; nf++) {                                      \
                    const uint32_t bb0 = (nf & 1) ? b4[nf >> 1][1] : b4[nf >> 1][0];  \
                    const uint32_t bb1 = (nf & 1) ? b4[nf >> 1][3] : b4[nf >> 1][2];  \
                    asm volatile(                                                     \
                        "mma.sync.aligned.m16n8k16.row.col.f32.bf16.bf16.f32 "        \
                        "{%0,%1,%2,%3}, {%4,%5,%6,%7}, {%8,%9}, {%0,%1,%2,%3};"       \
                        : "+f"(acc[mf][nf][0]), "+f"(acc[mf][nf][1]),                 \
                          "+f"(acc[mf][nf][2]), "+f"(acc[mf][nf][3])                  \
                        : "r"(a4[mf][0]), "r"(a4[mf][1]), "r"(a4[mf][2]), "r"(a4[mf][3]), \
                          "r"(bb0), "r"(bb1));                                        \
                }                                                                     \
            }                                                                         \
        }                                                                             \
    }                                                                                 \
    asm volatile("cp.async.wait_group 0;" ::: "memory");

__global__ void __launch_bounds__(256, 1)
mma256_ss(const __nv_bfloat16* __restrict__ A, const __nv_bfloat16* __restrict__ B,
          const float* __restrict__ bias, float* __restrict__ SS,
          int M, int N, int K)
{
    extern __shared__ char ds[];
    const uint32_t base = smem_u32(ds);
    const int tid  = threadIdx.x;
    const int lane = tid & 31;
    const int warp = tid >> 5;
    const int wm   = warp & 1;
    const int wn   = warp >> 1;
    const int m0 = blockIdx.y * 128, n0 = blockIdx.x * 256;

    float acc[4][8][4];
#pragma unroll
    for (int a = 0; a < 4; a++)
#pragma unroll
        for (int b = 0; b < 8; b++)
#pragma unroll
            for (int c = 0; c < 4; c++) acc[a][b][c] = 0.f;

    MMA256_CORE(A, B, K, M)

#pragma unroll
    for (int mf = 0; mf < 4; mf++) {
        const int r0 = m0 + wm * 64 + mf * 16 + (lane >> 2);
        float s0 = 0.f, s1 = 0.f;
#pragma unroll
        for (int nf = 0; nf < 8; nf++) {
            const int col = n0 + wn * 64 + nf * 8 + (lane & 3) * 2;
            const float b0 = __ldg(&bias[col]), b1 = __ldg(&bias[col + 1]);
            float v0 = acc[mf][nf][0] + b0, v1 = acc[mf][nf][1] + b1;
            float v2 = acc[mf][nf][2] + b0, v3 = acc[mf][nf][3] + b1;
            s0 += v0 * v0 + v1 * v1;
            s1 += v2 * v2 + v3 * v3;
        }
        s0 += __shfl_xor_sync(~0u, s0, 1); s0 += __shfl_xor_sync(~0u, s0, 2);
        s1 += __shfl_xor_sync(~0u, s1, 1); s1 += __shfl_xor_sync(~0u, s1, 2);
        if ((lane & 3) == 0) {
            if (r0 < M)     atomicAdd(&SS[r0], s0);
            if (r0 + 8 < M) atomicAdd(&SS[r0 + 8], s1);
        }
    }
}

__global__ void __launch_bounds__(256, 1)
mma256_z(const __nv_bfloat16* __restrict__ Ab, const __nv_bfloat16* __restrict__ Bb,
         const float* __restrict__ bias, float* __restrict__ Cb,
         int M, int N, int K, size_t sA, size_t sB, size_t sC)
{
    extern __shared__ char ds[];
    const uint32_t base = smem_u32(ds);
    const int tid  = threadIdx.x;
    const int lane = tid & 31;
    const int warp = tid >> 5;
    const int wm   = warp & 1;
    const int wn   = warp >> 1;
    const int blk  = blockIdx.z;
    const int m0 = blockIdx.y * 128, n0 = blockIdx.x * 256;

    const __nv_bfloat16* A = Ab + (size_t)blk * sA;
    const __nv_bfloat16* B = Bb + (size_t)blk * sB;
    float* C = Cb + (size_t)blk * sC;

    float acc[4][8][4];
#pragma unroll
    for (int a = 0; a < 4; a++)
#pragma unroll
        for (int b = 0; b < 8; b++)
#pragma unroll
            for (int c = 0; c < 4; c++) acc[a][b][c] = 0.f;

    MMA256_CORE(A, B, K, M)

#pragma unroll
    for (int mf = 0; mf < 4; mf++) {
        const int r0 = m0 + wm * 64 + mf * 16 + (lane >> 2);
#pragma unroll
        for (int nf = 0; nf < 8; nf++) {
            const int col = n0 + wn * 64 + nf * 8 + (lane & 3) * 2;
            const float b0 = __ldg(&bias[col]), b1 = __ldg(&bias[col + 1]);
            if (r0 < M) {
                float2 v = make_float2(acc[mf][nf][0] + b0, acc[mf][nf][1] + b1);
                *(float2*)(C + (size_t)r0 * N + col) = v;
            }
            if (r0 + 8 < M) {
                float2 v = make_float2(acc[mf][nf][2] + b0, acc[mf][nf][3] + b1);
                *(float2*)(C + (size_t)(r0 + 8) * N + col) = v;
            }
        }
    }
}

// ---------------------------------------------------------------------------
// SIMT fp32 GEMM for KV projections (z-merged)
// ---------------------------------------------------------------------------
__global__ void __launch_bounds__(256, 2)
gemm_kv(const float* __restrict__ A,
        const float* __restrict__ Wk, const float* __restrict__ bk, float* __restrict__ Ck,
        const float* __restrict__ Wv, const float* __restrict__ bv, float* __restrict__ Cv,
        int M, int N, int K)
{
    const float* B    = blockIdx.z ? Wv : Wk;
    const float* bias = blockIdx.z ? bv : bk;
    float* C          = blockIdx.z ? Cv : Ck;

    const int BM = 128, BN = 128, BK = 16;
    __shared__ float As[BK][BM + 4];
    __shared__ float Bs[BK][BN + 4];

    const int tid  = threadIdx.x;
    const int tx   = tid & 15;
    const int ty   = tid >> 4;
    const int col0 = blockIdx.x * BN;

    float acc[8][8];
#pragma unroll
    for (int i = 0; i < 8; i++)
#pragma unroll
        for (int j = 0; j < 8; j++) acc[i][j] = 0.f;

    for (int k0 = 0; k0 < K; k0 += BK) {
#pragma unroll
        for (int it = 0; it < 2; it++) {
            int i = tid + 256 * it;
            int r = i >> 2, c4 = i & 3;
            float4 v = make_float4(0.f, 0.f, 0.f, 0.f);
            if (r < M) v = *(const float4*)(A + (size_t)r * K + k0 + c4 * 4);
            As[c4 * 4 + 0][r] = v.x; As[c4 * 4 + 1][r] = v.y;
            As[c4 * 4 + 2][r] = v.z; As[c4 * 4 + 3][r] = v.w;
        }
#pragma unroll
        for (int it = 0; it < 2; it++) {
            int i = tid + 256 * it;
            int r = i >> 2, c4 = i & 3;
            float4 v = *(const float4*)(B + (size_t)(col0 + r) * K + k0 + c4 * 4);
            Bs[c4 * 4 + 0][r] = v.x; Bs[c4 * 4 + 1][r] = v.y;
            Bs[c4 * 4 + 2][r] = v.z; Bs[c4 * 4 + 3][r] = v.w;
        }
        __syncthreads();
#pragma unroll
        for (int kk = 0; kk < BK; kk++) {
            float a[8], b[8];
#pragma unroll
            for (int i = 0; i < 8; i++) a[i] = As[kk][ty * 8 + i];
#pragma unroll
            for (int j = 0; j < 8; j++) b[j] = Bs[kk][tx * 8 + j];
#pragma unroll
            for (int i = 0; i < 8; i++)
#pragma unroll
                for (int j = 0; j < 8; j++)
                    acc[i][j] = fmaf(a[i], b[j], acc[i][j]);
        }
        __syncthreads();
    }
#pragma unroll
    for (int i = 0; i < 8; i++) {
        int r = ty * 8 + i;
        if (r >= M) continue;
#pragma unroll
        for (int j4 = 0; j4 < 2; j4++) {
            int c = col0 + tx * 8 + j4 * 4;
            float4 o;
            o.x = acc[i][j4 * 4 + 0] + bias[c + 0];
            o.y = acc[i][j4 * 4 + 1] + bias[c + 1];
            o.z = acc[i][j4 * 4 + 2] + bias[c + 2];
            o.w = acc[i][j4 * 4 + 3] + bias[c + 3];
            *(float4*)(C + (size_t)r * N + c) = o;
        }
    }
}

// ---------------------------------------------------------------------------
// VTg[blk][n][h*16+j] = sum_d v[blk*16+j, h*128+d] * Wo[n, h*128+d]
// ---------------------------------------------------------------------------
__global__ void __launch_bounds__(256, 2)
vproj_kernel(const float* __restrict__ V, const float* __restrict__ Wo,
             float* __restrict__ VTg)
{
    const int h  = blockIdx.y;
    const int n0 = blockIdx.x * 128;
    const int tid = threadIdx.x;
    const int tx = tid & 15;
    const int ty = tid >> 4;

    __shared__ float As[16][96 + 4];
    __shared__ float Bs[16][128 + 4];

    float acc[6][8];
#pragma unroll
    for (int i = 0; i < 6; i++)
#pragma unroll
        for (int j = 0; j < 8; j++) acc[i][j] = 0.f;

    for (int kc = 0; kc < 8; kc++) {
        const int kbase = h * HD + kc * 16;
#pragma unroll
        for (int it = 0; it < 2; it++) {
            int i = tid + 256 * it;
            if (i < 384) {
                int r = i >> 2, c4 = i & 3;
                float4 v = *(const float4*)(V + (size_t)r * DIMV + kbase + c4 * 4);
                As[c4 * 4 + 0][r] = v.x; As[c4 * 4 + 1][r] = v.y;
                As[c4 * 4 + 2][r] = v.z; As[c4 * 4 + 3][r] = v.w;
            }
        }
#pragma unroll
        for (int it = 0; it < 2; it++) {
            int i = tid + 256 * it;
            int r = i >> 2, c4 = i & 3;
            float4 v = *(const float4*)(Wo + (size_t)(n0 + r) * DIMV + kbase + c4 * 4);
            Bs[c4 * 4 + 0][r] = v.x; Bs[c4 * 4 + 1][r] = v.y;
            Bs[c4 * 4 + 2][r] = v.z; Bs[c4 * 4 + 3][r] = v.w;
        }
        __syncthreads();
#pragma unroll
        for (int kk = 0; kk < 16; kk++) {
            float a[6], b[8];
#pragma unroll
            for (int i = 0; i < 6; i++) a[i] = As[kk][ty * 6 + i];
#pragma unroll
            for (int j = 0; j < 8; j++) b[j] = Bs[kk][tx * 8 + j];
#pragma unroll
            for (int i = 0; i < 6; i++)
#pragma unroll
                for (int j = 0; j < 8; j++)
                    acc[i][j] = fmaf(a[i], b[j], acc[i][j]);
        }
        __syncthreads();
    }

#pragma unroll
    for (int i = 0; i < 6; i++) {
        const int jg = ty * 6 + i;
        float* dst = VTg + (size_t)(jg >> 4) * DIMV * NCOLS + h * NKV + (jg & 15);
#pragma unroll
        for (int j = 0; j < 8; j++)
            dst[(size_t)(n0 + tx * 8 + j) * NCOLS] = acc[i][j];
    }
}

// ---------------------------------------------------------------------------
// uproj: emits U3 split-3 (hi,hi,lo) directly, coalesced 48B uint4 stores.
// ---------------------------------------------------------------------------
__global__ void __launch_bounds__(256, 2)
uproj_kernel(const float* __restrict__ Kn, const float* __restrict__ Wq,
             const float* __restrict__ gq, __nv_bfloat16* __restrict__ U3)
{
    const int h  = blockIdx.y;
    const int m0 = blockIdx.x * 128;
    const int tid = threadIdx.x;
    const int tx = tid & 15;
    const int ty = tid >> 4;

    __shared__ float As[16][96 + 4];
    __shared__ float Bs[16][128 + 4];

    float acc[6][8];
#pragma unroll
    for (int i = 0; i < 6; i++)
#pragma unroll
        for (int j = 0; j < 8; j++) acc[i][j] = 0.f;

    for (int kc = 0; kc < 8; kc++) {
        const int kbase = h * HD + kc * 16;
#pragma unroll
        for (int it = 0; it < 2; it++) {
            int i = tid + 256 * it;
            if (i < 384) {
                int r = i >> 2, c4 = i & 3;
                float4 v = *(const float4*)(Kn + (size_t)r * DIMV + kbase + c4 * 4);
                float4 g = *(const float4*)(gq + kbase + c4 * 4);
                As[c4 * 4 + 0][r] = v.x * g.x; As[c4 * 4 + 1][r] = v.y * g.y;
                As[c4 * 4 + 2][r] = v.z * g.z; As[c4 * 4 + 3][r] = v.w * g.w;
            }
        }
#pragma unroll
        for (int it = 0; it < 2; it++) {
            int i = tid + 256 * it;
            int kr = i >> 5, c4 = i & 31;
            float4 v = *(const float4*)(Wq + (size_t)(kbase + kr) * DIMV + m0 + c4 * 4);
            Bs[kr][c4 * 4 + 0] = v.x; Bs[kr][c4 * 4 + 1] = v.y;
            Bs[kr][c4 * 4 + 2] = v.z; Bs[kr][c4 * 4 + 3] = v.w;
        }
        __syncthreads();
#pragma unroll
        for (int kk = 0; kk < 16; kk++) {
            float a[6], b[8];
#pragma unroll
            for (int i = 0; i < 6; i++) a[i] = As[kk][ty * 6 + i];
#pragma unroll
            for (int j = 0; j < 8; j++) b[j] = Bs[kk][tx * 8 + j];
#pragma unroll
            for (int i = 0; i < 6; i++)
#pragma unroll
                for (int j = 0; j < 8; j++)
                    acc[i][j] = fmaf(a[i], b[j], acc[i][j]);
        }
        __syncthreads();
    }

#pragma unroll
    for (int i = 0; i < 6; i++) {
        const int jg  = ty * 6 + i;
        const int row = (jg >> 4) * NCOLS + h * NKV + (jg & 15);
        union { __nv_bfloat16 hh[24]; uint4 u[3]; } o;
#pragma unroll
        for (int j = 0; j < 8; j++) {
            float f = acc[i][j];
            __nv_bfloat16 hi = __float2bfloat16(f);
            __nv_bfloat16 lo = __float2bfloat16(f - __bfloat162float(hi));
            o.hh[3*j] = hi; o.hh[3*j+1] = hi; o.hh[3*j+2] = lo;
        }
        uint4* dst = (uint4*)(U3 + (size_t)row * K2 + 3 * (m0 + tx * 8));
        dst[0] = o.u[0]; dst[1] = o.u[1]; dst[2] = o.u[2];
    }
}

__global__ void __launch_bounds__(256)
cb_kernel(const float* __restrict__ Kn, const float* __restrict__ bq,
          const float* __restrict__ gq, float* __restrict__ CB)
{
    int col = blockIdx.x * blockDim.x + threadIdx.x;
    if (col >= NUALL) return;
    int blk = col / NCOLS, rem = col % NCOLS;
    int h = rem >> 4, j = rem & 15;
    int jg = blk * NKV + j;
    const float* kp = Kn + (size_t)jg * DIMV + h * HD;
    const float* bp = bq + h * HD;
    const float* gp = gq + h * HD;
    float s = 0.f;
#pragma unroll 4
    for (int d = 0; d < HD; d++) s = fmaf(bp[d] * gp[d], kp[d], s);
    CB[col] = s;
}

// ---------------------------------------------------------------------------
// softmax: emit P as split-3 bf16 (hi,lo,hi)
// ---------------------------------------------------------------------------
__global__ void __launch_bounds__(256)
softmax_p3(const float* __restrict__ LG, const float* __restrict__ SS,
           __nv_bfloat16* __restrict__ P3)
{
    int gid = blockIdx.x * blockDim.x + threadIdx.x;
    if (gid >= L1V * NH) return;
    int t = gid / NH, h = gid % NH;
    const float s = rsqrtf(SS[t] * (1.0f / DIMV) + 1e-6f) * 0.08838834764831845f;
    const float* lp = LG + (size_t)t * NCOLS + h * NKV;
    float lg[NKV];
#pragma unroll
    for (int j4 = 0; j4 < 4; j4++) {
        float4 v = *(const float4*)(lp + j4 * 4);
        lg[j4*4+0] = v.x * s; lg[j4*4+1] = v.y * s;
        lg[j4*4+2] = v.z * s; lg[j4*4+3] = v.w * s;
    }
    float m = lg[0];
#pragma unroll
    for (int j = 1; j < NKV; j++) m = fmaxf(m, lg[j]);
    float sum = 0.f;
#pragma unroll
    for (int j = 0; j < NKV; j++) { lg[j] = expf(lg[j] - m); sum += lg[j]; }
    const float inv = 1.f / sum;

    union { __nv_bfloat16 h48[48]; uint4 u[6]; } o;
#pragma unroll
    for (int j = 0; j < NKV; j++) {
        float p = lg[j] * inv;
        __nv_bfloat16 hi = __float2bfloat16(p);
        __nv_bfloat16 lo = __float2bfloat16(p - __bfloat162float(hi));
        o.h48[3*j] = hi; o.h48[3*j+1] = lo; o.h48[3*j+2] = hi;
    }
    uint4* dst = (uint4*)(P3 + (size_t)t * K3P + h * 48);
#pragma unroll
    for (int i = 0; i < 6; i++) dst[i] = o.u[i];
}

// ---------------------------------------------------------------------------
// rmsnorm (in-place) — K only
// ---------------------------------------------------------------------------
__global__ void __launch_bounds__(256)
rmsnorm_rows(float* __restrict__ X, const float* __restrict__ g)
{
    const int row = blockIdx.x;
    float* x = X + (size_t)row * DIMV;

    float ss = 0.f;
    for (int i = threadIdx.x; i < DIMV / 4; i += 256) {
        float4 v = ((const float4*)x)[i];
        ss += v.x * v.x + v.y * v.y + v.z * v.z + v.w * v.w;
    }
#pragma unroll
    for (int o = 16; o > 0; o >>= 1) ss += __shfl_xor_sync(~0u, ss, o);
    __shared__ float red[8];
    if ((threadIdx.x & 31) == 0) red[threadIdx.x >> 5] = ss;
    __syncthreads();
    if (threadIdx.x < 8) {
        float v = red[threadIdx.x];
#pragma unroll
        for (int o = 4; o > 0; o >>= 1) v += __shfl_xor_sync(0xffu, v, o);
        if (threadIdx.x == 0) red[0] = v;
    }
    __syncthreads();
    const float scale = rsqrtf(red[0] * (1.0f / DIMV) + 1e-6f);

    for (int i = threadIdx.x; i < DIMV / 4; i += 256) {
        float4 v  = ((const float4*)x)[i];
        float4 gg = ((const float4*)g)[i];
        v.x *= scale * gg.x; v.y *= scale * gg.y;
        v.z *= scale * gg.z; v.w *= scale * gg.w;
        ((float4*)x)[i] = v;
    }
}

// ---------------------------------------------------------------------------
// launch — round-11 winner, verbatim
// ---------------------------------------------------------------------------
extern "C" void kernel_launch(void* const* d_in, const int* in_sizes, int n_in,
                              void* d_out, int out_size)
{
    (void)in_sizes; (void)n_in; (void)out_size;
    const float* x   = (const float*)d_in[0];
    const float* ctx = (const float*)d_in[1];
    const float* Wq = (const float*)d_in[6];
    const float* bq = (const float*)d_in[7];
    const float* Wk = (const float*)d_in[8];
    const float* bk = (const float*)d_in[9];
    const float* Wv = (const float*)d_in[10];
    const float* bv = (const float*)d_in[11];
    const float* Wo = (const float*)d_in[12];
    const float* bo = (const float*)d_in[13];
    const float* gq = (const float*)d_in[14];
    const float* gk = (const float*)d_in[15];
    float* out = (float*)d_out;

    float *kb, *vb, *vtg, *cb, *ssb, *lgb;
    __nv_bfloat16 *xb, *wb, *x3, *u3, *p3, *vt3;
    cudaGetSymbolAddress((void**)&kb,  g_k);
    cudaGetSymbolAddress((void**)&vb,  g_v);
    cudaGetSymbolAddress((void**)&vtg, g_vtg);
    cudaGetSymbolAddress((void**)&cb,  g_cb);
    cudaGetSymbolAddress((void**)&ssb, g_ss);
    cudaGetSymbolAddress((void**)&lgb, g_lg);
    cudaGetSymbolAddress((void**)&xb,  g_xb);
    cudaGetSymbolAddress((void**)&wb,  g_wb);
    cudaGetSymbolAddress((void**)&x3,  g_x3);
    cudaGetSymbolAddress((void**)&u3,  g_u3);
    cudaGetSymbolAddress((void**)&p3,  g_p3);
    cudaGetSymbolAddress((void**)&vt3, g_vt3);

    const int dynsmem  = STG * STAGEB;
    const int dynsmem2 = STG2 * STAGE2B;

    static cudaStream_t sB = nullptr;
    static cudaEvent_t  e0 = nullptr, eW = nullptr, eB = nullptr;
    if (sB == nullptr) {
        cudaStreamCreateWithFlags(&sB, cudaStreamNonBlocking);
        cudaEventCreateWithFlags(&e0, cudaEventDisableTiming);
        cudaEventCreateWithFlags(&eW, cudaEventDisableTiming);
        cudaEventCreateWithFlags(&eB, cudaEventDisableTiming);
        cudaFuncSetAttribute(mma_gemm_z, cudaFuncAttributeMaxDynamicSharedMemorySize, dynsmem);
        cudaFuncSetAttribute(mma256_ss, cudaFuncAttributeMaxDynamicSharedMemorySize, dynsmem2);
        cudaFuncSetAttribute(mma256_z,  cudaFuncAttributeMaxDynamicSharedMemorySize, dynsmem2);
    }

    // fork
    cudaEventRecord(e0, 0);
    cudaStreamWaitEvent(sB, e0, 0);

    // side stream B: Wq->bf16 + ss zero first (norm GEMM waits on eW),
    // then the KV prep chain (uproj emits u3 directly).
    zero_f32<<<(L1V + 255) / 256, 256, 0, sB>>>(ssb, L1V);
    cvt_bf16<<<2048, 256, 0, sB>>>(Wq, wb, (size_t)DIMV * DIMV / 8);
    cudaEventRecord(eW, sB);
    {
        dim3 grid(DIMV / 128, 1, 2);
        gemm_kv<<<grid, 256, 0, sB>>>(ctx, Wk, bk, kb, Wv, bv, vb, LAV, DIMV, KVDIM);
    }
    rmsnorm_rows<<<LAV, 256, 0, sB>>>(kb, gk);
    {
        dim3 grid(DIMV / 128, NH);
        vproj_kernel<<<grid, 256, 0, sB>>>(vb, Wo, vtg);
        uproj_kernel<<<grid, 256, 0, sB>>>(kb, Wq, gq, u3);
    }
    cb_kernel<<<(NUALL + 255) / 256, 256, 0, sB>>>(kb, bq, gq, cb);
    cvt_split3<1><<<2048, 256, 0, sB>>>(vtg, vt3, (size_t)NBLK * DIMV * NCOLS / 8);
    cudaEventRecord(eB, sB);

    // main: x conversion + norm GEMM (side chain hides underneath)
    cvt_x_fused<<<2048, 256>>>(x, xb, x3, (size_t)L1V * DIMV / 8);
    cudaStreamWaitEvent(0, eW, 0);
    {
        dim3 grid(DIMV / 256, (L1V + 127) / 128);
        mma256_ss<<<grid, 256, dynsmem2>>>(xb, wb, bq, ssb, L1V, DIMV, DIMV);
    }

    // join, then logits -> softmax -> P@VT
    cudaStreamWaitEvent(0, eB, 0);
    {
        dim3 grid(NCOLS / 128, (HWQ + 127) / 128, NBLK);
        mma_gemm_z<<<grid, 256, dynsmem>>>(
            x3, u3, cb, lgb, HWQ, NCOLS, K2,
            (size_t)HWQ * K2, (size_t)NCOLS * K2, (size_t)HWQ * NCOLS, NCOLS);
    }
    softmax_p3<<<(L1V * NH + 255) / 256, 256>>>(lgb, ssb, p3);
    {
        dim3 grid(DIMV / 256, (HWQ + 127) / 128, NBLK);
        mma256_z<<<grid, 256, dynsmem2>>>(
            p3, vt3, bo, out, HWQ, DIMV, K3P,
            (size_t)HWQ * K3P, (size_t)DIMV * K3P, (size_t)HWQ * DIMV);
    }
}

// round 15
// speedup vs baseline: 1.5796x; 1.0038x over previous
#include <cuda_runtime.h>
#include <cuda_bf16.h>
#include <math.h>
#include <stdint.h>

#define DIMV   5120
#define KVDIM  1536
#define NH     40
#define HD     128
#define L1V    9360
#define LAV    96
#define NBLK   6
#define NKV    16
#define HWQ    1560
#define K2     (3 * DIMV)
#define NCOLS  (NH * NKV)
#define K3P    (3 * NCOLS)
#define NUALL  (NBLK * NCOLS)
#define NKSPL  3               // K-split factor for logits GEMM

// ---------------- scratch ----------------------------------------------------
__device__ float g_k[(size_t)LAV * DIMV];
__device__ float g_v[(size_t)LAV * DIMV];
__device__ float g_vtg[(size_t)NBLK * DIMV * NCOLS];
__device__ float g_cb[NUALL];
__device__ float g_ss[L1V];
__device__ float g_lg[(size_t)L1V * NCOLS];
__device__ __nv_bfloat16 g_xb[(size_t)L1V * DIMV];
__device__ __nv_bfloat16 g_wb[(size_t)DIMV * DIMV];
__device__ __nv_bfloat16 g_x3[(size_t)L1V * K2];
__device__ __nv_bfloat16 g_u3[(size_t)NUALL * K2];
__device__ __nv_bfloat16 g_p3[(size_t)L1V * K3P];
__device__ __nv_bfloat16 g_vt3[(size_t)NBLK * DIMV * K3P];

// ---------------- helpers ----------------------------------------------------
__device__ __forceinline__ uint32_t smem_u32(const void* p) {
    uint32_t a;
    asm("{ .reg .u64 t; cvta.to.shared.u64 t, %1; cvt.u32.u64 %0, t; }" : "=r"(a) : "l"(p));
    return a;
}
__device__ __forceinline__ void cp16(uint32_t dst, const void* src, int srcsize) {
    asm volatile("cp.async.cg.shared.global [%0], [%1], 16, %2;"
                 :: "r"(dst), "l"(src), "r"(srcsize) : "memory");
}

// ---------------------------------------------------------------------------
// converters
// ---------------------------------------------------------------------------
__global__ void __launch_bounds__(256)
cvt_x_fused(const float* __restrict__ X, __nv_bfloat16* __restrict__ XB,
            __nv_bfloat16* __restrict__ X3, size_t n8)
{
    size_t i = (size_t)blockIdx.x * blockDim.x + threadIdx.x;
    const size_t stride = (size_t)gridDim.x * blockDim.x;
    for (; i < n8; i += stride) {
        const float4* src = (const float4*)X + i * 2;
        float4 v0 = src[0], v1 = src[1];
        float f[8] = {v0.x, v0.y, v0.z, v0.w, v1.x, v1.y, v1.z, v1.w};
        union { __nv_bfloat16 h[8];  uint4 u; }    ob;
        union { __nv_bfloat16 h[24]; uint4 u[3]; } o3;
#pragma unroll
        for (int j = 0; j < 8; j++) {
            __nv_bfloat16 hi = __float2bfloat16(f[j]);
            __nv_bfloat16 lo = __float2bfloat16(f[j] - __bfloat162float(hi));
            ob.h[j] = hi;
            o3.h[3*j] = hi; o3.h[3*j+1] = lo; o3.h[3*j+2] = hi;
        }
        ((uint4*)XB)[i] = ob.u;
        uint4* dst = (uint4*)(X3 + i * 24);
        dst[0] = o3.u[0]; dst[1] = o3.u[1]; dst[2] = o3.u[2];
    }
}

__global__ void __launch_bounds__(256)
cvt_bf16(const float* __restrict__ X, __nv_bfloat16* __restrict__ Y, size_t n8)
{
    size_t i = (size_t)blockIdx.x * blockDim.x + threadIdx.x;
    const size_t stride = (size_t)gridDim.x * blockDim.x;
    for (; i < n8; i += stride) {
        const float4* src = (const float4*)X + i * 2;
        float4 v0 = src[0], v1 = src[1];
        union { __nv_bfloat162 h[4]; uint4 u; } o;
        o.h[0] = __nv_bfloat162(__float2bfloat16(v0.x), __float2bfloat16(v0.y));
        o.h[1] = __nv_bfloat162(__float2bfloat16(v0.z), __float2bfloat16(v0.w));
        o.h[2] = __nv_bfloat162(__float2bfloat16(v1.x), __float2bfloat16(v1.y));
        o.h[3] = __nv_bfloat162(__float2bfloat16(v1.z), __float2bfloat16(v1.w));
        ((uint4*)Y)[i] = o.u;
    }
}

template <int PAT>   // 0: (hi,lo,hi); 1: (hi,hi,lo)
__global__ void __launch_bounds__(256)
cvt_split3(const float* __restrict__ X, __nv_bfloat16* __restrict__ Y, size_t n8)
{
    size_t i = (size_t)blockIdx.x * blockDim.x + threadIdx.x;
    const size_t stride = (size_t)gridDim.x * blockDim.x;
    for (; i < n8; i += stride) {
        const float4* src = (const float4*)X + i * 2;
        float4 v0 = src[0], v1 = src[1];
        float f[8] = {v0.x, v0.y, v0.z, v0.w, v1.x, v1.y, v1.z, v1.w};
        union { __nv_bfloat16 h[24]; uint4 u[3]; } o;
#pragma unroll
        for (int j = 0; j < 8; j++) {
            __nv_bfloat16 hi = __float2bfloat16(f[j]);
            __nv_bfloat16 lo = __float2bfloat16(f[j] - __bfloat162float(hi));
            if (PAT == 0) { o.h[3*j] = hi; o.h[3*j+1] = lo; o.h[3*j+2] = hi; }
            else          { o.h[3*j] = hi; o.h[3*j+1] = hi; o.h[3*j+2] = lo; }
        }
        uint4* dst = (uint4*)(Y + i * 24);
        dst[0] = o.u[0]; dst[1] = o.u[1]; dst[2] = o.u[2];
    }
}

__global__ void __launch_bounds__(256)
zero_f32(float* __restrict__ p, size_t n4)
{
    size_t i = (size_t)blockIdx.x * blockDim.x + threadIdx.x;
    const size_t stride = (size_t)gridDim.x * blockDim.x;
    for (; i < n4; i += stride)
        ((float4*)p)[i] = make_float4(0.f, 0.f, 0.f, 0.f);
}

// ---------------------------------------------------------------------------
// 128x128 HMMA core, K-split logits GEMM: partial sums atomically added to LG.
// z encodes (blk, kc): blk = z / NKSPL, kc = z % NKSPL.
// Row stride is K2; this chunk covers K columns [kc*DIMV, (kc+1)*DIMV).
// ---------------------------------------------------------------------------
#define BMg 128
#define BKg 32
#define STG 3
#define ROWB  80
#define TILEB (BMg * ROWB)
#define STAGEB (2 * TILEB)

__global__ void __launch_bounds__(256, 2)
mma_logits_ks(const __nv_bfloat16* __restrict__ X3, const __nv_bfloat16* __restrict__ U3,
              float* __restrict__ LG)
{
    extern __shared__ char ds[];
    const uint32_t base = smem_u32(ds);
    const int tid  = threadIdx.x;
    const int lane = tid & 31;
    const int warp = tid >> 5;
    const int wm   = warp & 3;
    const int wn   = warp >> 2;
    const int blk  = blockIdx.z / NKSPL;
    const int kc   = blockIdx.z % NKSPL;
    const int m0 = blockIdx.y * BMg, n0 = blockIdx.x * BMg;

    const __nv_bfloat16* A = X3 + (size_t)blk * HWQ * K2 + (size_t)kc * DIMV;
    const __nv_bfloat16* B = U3 + (size_t)blk * NCOLS * K2 + (size_t)kc * DIMV;

    float acc[2][8][4];
#pragma unroll
    for (int a = 0; a < 2; a++)
#pragma unroll
        for (int b = 0; b < 8; b++)
#pragma unroll
            for (int c = 0; c < 4; c++) acc[a][b][c] = 0.f;

    const int lrow = tid >> 1;
    const int lc   = (tid & 1) * 2;
    auto load_stage = [&](int s, int k0) {
        const uint32_t sa = base + (uint32_t)s * STAGEB;
        const uint32_t sb = sa + TILEB;
        const __nv_bfloat16* ga = A + (size_t)(m0 + lrow) * K2 + k0 + lc * 8;
        const int pa = (m0 + lrow) < HWQ ? 16 : 0;
        cp16(sa + lrow * ROWB + lc * 16,       ga,     pa);
        cp16(sa + lrow * ROWB + (lc + 1) * 16, ga + 8, pa);
        const __nv_bfloat16* gb = B + (size_t)(n0 + lrow) * K2 + k0 + lc * 8;
        cp16(sb + lrow * ROWB + lc * 16,       gb,     16);
        cp16(sb + lrow * ROWB + (lc + 1) * 16, gb + 8, 16);
    };
    const int niter = DIMV / BKg;   // 160
#pragma unroll
    for (int s = 0; s < STG - 1; s++) {
        load_stage(s, s * BKg);
        asm volatile("cp.async.commit_group;" ::: "memory");
    }
    for (int it = 0; it < niter; it++) {
        asm volatile("cp.async.wait_group %0;" :: "n"(STG - 2) : "memory");
        __syncthreads();
        const int pf = it + STG - 1;
        if (pf < niter) load_stage(pf % STG, pf * BKg);
        asm volatile("cp.async.commit_group;" ::: "memory");
        const uint32_t sa = base + (uint32_t)(it % STG) * STAGEB;
        const uint32_t sb = sa + TILEB;
#pragma unroll
        for (int h = 0; h < 2; h++) {
            uint32_t a[2][4], b4[4][4];
            const int koff = (h * 16 + ((lane >> 4) * 8)) * 2;
#pragma unroll
            for (int mf = 0; mf < 2; mf++) {
                uint32_t addr = sa + (wm * 32 + mf * 16 + (lane & 15)) * ROWB + koff;
                asm volatile("ldmatrix.sync.aligned.m8n8.x4.shared.b16 {%0,%1,%2,%3}, [%4];"
                             : "=r"(a[mf][0]), "=r"(a[mf][1]), "=r"(a[mf][2]), "=r"(a[mf][3])
                             : "r"(addr));
            }
#pragma unroll
            for (int nb = 0; nb < 4; nb++) {
                uint32_t addr = sb + (wn * 64 + nb * 16 + (lane & 15)) * ROWB + koff;
                asm volatile("ldmatrix.sync.aligned.m8n8.x4.shared.b16 {%0,%1,%2,%3}, [%4];"
                             : "=r"(b4[nb][0]), "=r"(b4[nb][1]), "=r"(b4[nb][2]), "=r"(b4[nb][3])
                             : "r"(addr));
            }
#pragma unroll
            for (int mf = 0; mf < 2; mf++) {
#pragma unroll
                for (int nf = 0; nf < 8; nf++) {
                    const uint32_t bb0 = (nf & 1) ? b4[nf >> 1][1] : b4[nf >> 1][0];
                    const uint32_t bb1 = (nf & 1) ? b4[nf >> 1][3] : b4[nf >> 1][2];
                    asm volatile(
                        "mma.sync.aligned.m16n8k16.row.col.f32.bf16.bf16.f32 "
                        "{%0,%1,%2,%3}, {%4,%5,%6,%7}, {%8,%9}, {%0,%1,%2,%3};"
                        : "+f"(acc[mf][nf][0]), "+f"(acc[mf][nf][1]),
                          "+f"(acc[mf][nf][2]), "+f"(acc[mf][nf][3])
                        : "r"(a[mf][0]), "r"(a[mf][1]), "r"(a[mf][2]), "r"(a[mf][3]),
                          "r"(bb0), "r"(bb1));
                }
            }
        }
    }
    asm volatile("cp.async.wait_group 0;" ::: "memory");

    // epilogue: atomic accumulation of partial sums (no bias; added in softmax)
    float* Cb = LG + (size_t)blk * HWQ * NCOLS;
#pragma unroll
    for (int mf = 0; mf < 2; mf++) {
        const int r0 = m0 + wm * 32 + mf * 16 + (lane >> 2);
#pragma unroll
        for (int nf = 0; nf < 8; nf++) {
            const int col = n0 + wn * 64 + nf * 8 + (lane & 3) * 2;
            if (r0 < HWQ) {
                atomicAdd(Cb + (size_t)r0 * NCOLS + col,     acc[mf][nf][0]);
                atomicAdd(Cb + (size_t)r0 * NCOLS + col + 1, acc[mf][nf][1]);
            }
            if (r0 + 8 < HWQ) {
                atomicAdd(Cb + (size_t)(r0 + 8) * NCOLS + col,     acc[mf][nf][2]);
                atomicAdd(Cb + (size_t)(r0 + 8) * NCOLS + col + 1, acc[mf][nf][3]);
            }
        }
    }
}

// ---------------------------------------------------------------------------
// 128x256 HMMA core (norm GEMM, P@VT)
// ---------------------------------------------------------------------------
#define A2B    10240
#define STAGE2B 30720
#define STG2   3

#define MMA256_CORE(A_, B_, Kdim_, Mbound_)                                           \
    auto load_stage = [&](int s, int k0) {                                            \
        const uint32_t sa = base + (uint32_t)s * STAGE2B;                             \
        const uint32_t sb = sa + A2B;                                                 \
        _Pragma("unroll")                                                             \
        for (int it2 = 0; it2 < 6; it2++) {                                           \
            int idx = tid + 256 * it2;                                                \
            int row = idx >> 2, c = idx & 3;                                          \
            if (row < 128) {                                                          \
                const __nv_bfloat16* g = A_ + (size_t)(m0 + row) * Kdim_ + k0 + c * 8;\
                cp16(sa + row * 80 + c * 16, g, (m0 + row) < Mbound_ ? 16 : 0);       \
            } else {                                                                  \
                int br = row - 128;                                                   \
                const __nv_bfloat16* g = B_ + (size_t)(n0 + br) * Kdim_ + k0 + c * 8; \
                cp16(sb + br * 80 + c * 16, g, 16);                                   \
            }                                                                         \
        }                                                                             \
    };                                                                                \
    const int niter = Kdim_ / 32;                                                     \
    _Pragma("unroll")                                                                 \
    for (int s = 0; s < STG2 - 1; s++) {                                              \
        load_stage(s, s * 32);                                                        \
        asm volatile("cp.async.commit_group;" ::: "memory");                          \
    }                                                                                 \
    for (int it = 0; it < niter; it++) {                                              \
        asm volatile("cp.async.wait_group %0;" :: "n"(STG2 - 2) : "memory");          \
        __syncthreads();                                                              \
        const int pf = it + STG2 - 1;                                                 \
        if (pf < niter) load_stage(pf % STG2, pf * 32);                               \
        asm volatile("cp.async.commit_group;" ::: "memory");                          \
        const uint32_t sa = base + (uint32_t)(it % STG2) * STAGE2B;                   \
        const uint32_t sb = sa + A2B;                                                 \
        _Pragma("unroll")                                                             \
        for (int h = 0; h < 2; h++) {                                                 \
            uint32_t a4[4][4], b4[4][4];                                              \
            const int koff = (h * 16 + ((lane >> 4) * 8)) * 2;                        \
            _Pragma("unroll")                                                         \
            for (int mf = 0; mf < 4; mf++) {                                          \
                uint32_t addr = sa + (wm * 64 + mf * 16 + (lane & 15)) * 80 + koff;   \
                asm volatile("ldmatrix.sync.aligned.m8n8.x4.shared.b16 {%0,%1,%2,%3}, [%4];" \
                             : "=r"(a4[mf][0]), "=r"(a4[mf][1]), "=r"(a4[mf][2]), "=r"(a4[mf][3]) \
                             : "r"(addr));                                            \
            }                                                                         \
            _Pragma("unroll")                                                         \
            for (int nb = 0; nb < 4; nb++) {                                          \
                uint32_t addr = sb + (wn * 64 + nb * 16 + (lane & 15)) * 80 + koff;   \
                asm volatile("ldmatrix.sync.aligned.m8n8.x4.shared.b16 {%0,%1,%2,%3}, [%4];" \
                             : "=r"(b4[nb][0]), "=r"(b4[nb][1]), "=r"(b4[nb][2]), "=r"(b4[nb][3]) \
                             : "r"(addr));                                            \
            }                                                                         \
            _Pragma("unroll")                                                         \
            for (int mf = 0; mf < 4; mf++) {                                          \
                _Pragma("unroll")                                                     \
                for (int nf = 0; nf < 8; nf++) {                                      \
                    const uint32_t bb0 = (nf & 1) ? b4[nf >> 1][1] : b4[nf >> 1][0];  \
                    const uint32_t bb1 = (nf & 1) ? b4[nf >> 1][3] : b4[nf >> 1][2];  \
                    asm volatile(                                                     \
                        "mma.sync.aligned.m16n8k16.row.col.f32.bf16.bf16.f32 "        \
                        "{%0,%1,%2,%3}, {%4,%5,%6,%7}, {%8,%9}, {%0,%1,%2,%3};"       \
                        : "+f"(acc[mf][nf][0]), "+f"(acc[mf][nf][1]),                 \
                          "+f"(acc[mf][nf][2]), "+f"(acc[mf][nf][3])                  \
                        : "r"(a4[mf][0]), "r"(a4[mf][1]), "r"(a4[mf][2]), "r"(a4[mf][3]), \
                          "r"(bb0), "r"(bb1));                                        \
                }                                                                     \
            }                                                                         \
        }                                                                             \
    }                                                                                 \
    asm volatile("cp.async.wait_group 0;" ::: "memory");

__global__ void __launch_bounds__(256, 1)
mma256_ss(const __nv_bfloat16* __restrict__ A, const __nv_bfloat16* __restrict__ B,
          const float* __restrict__ bias, float* __restrict__ SS,
          int M, int N, int K)
{
    extern __shared__ char ds[];
    const uint32_t base = smem_u32(ds);
    const int tid  = threadIdx.x;
    const int lane = tid & 31;
    const int warp = tid >> 5;
    const int wm   = warp & 1;
    const int wn   = warp >> 1;
    const int m0 = blockIdx.y * 128, n0 = blockIdx.x * 256;

    float acc[4][8][4];
#pragma unroll
    for (int a = 0; a < 4; a++)
#pragma unroll
        for (int b = 0; b < 8; b++)
#pragma unroll
            for (int c = 0; c < 4; c++) acc[a][b][c] = 0.f;

    MMA256_CORE(A, B, K, M)

#pragma unroll
    for (int mf = 0; mf < 4; mf++) {
        const int r0 = m0 + wm * 64 + mf * 16 + (lane >> 2);
        float s0 = 0.f, s1 = 0.f;
#pragma unroll
        for (int nf = 0; nf < 8; nf++) {
            const int col = n0 + wn * 64 + nf * 8 + (lane & 3) * 2;
            const float b0 = __ldg(&bias[col]), b1 = __ldg(&bias[col + 1]);
            float v0 = acc[mf][nf][0] + b0, v1 = acc[mf][nf][1] + b1;
            float v2 = acc[mf][nf][2] + b0, v3 = acc[mf][nf][3] + b1;
            s0 += v0 * v0 + v1 * v1;
            s1 += v2 * v2 + v3 * v3;
        }
        s0 += __shfl_xor_sync(~0u, s0, 1); s0 += __shfl_xor_sync(~0u, s0, 2);
        s1 += __shfl_xor_sync(~0u, s1, 1); s1 += __shfl_xor_sync(~0u, s1, 2);
        if ((lane & 3) == 0) {
            if (r0 < M)     atomicAdd(&SS[r0], s0);
            if (r0 + 8 < M) atomicAdd(&SS[r0 + 8], s1);
        }
    }
}

__global__ void __launch_bounds__(256, 1)
mma256_z(const __nv_bfloat16* __restrict__ Ab, const __nv_bfloat16* __restrict__ Bb,
         const float* __restrict__ bias, float* __restrict__ Cb,
         int M, int N, int K, size_t sA, size_t sB, size_t sC)
{
    extern __shared__ char ds[];
    const uint32_t base = smem_u32(ds);
    const int tid  = threadIdx.x;
    const int lane = tid & 31;
    const int warp = tid >> 5;
    const int wm   = warp & 1;
    const int wn   = warp >> 1;
    const int blk  = blockIdx.z;
    const int m0 = blockIdx.y * 128, n0 = blockIdx.x * 256;

    const __nv_bfloat16* A = Ab + (size_t)blk * sA;
    const __nv_bfloat16* B = Bb + (size_t)blk * sB;
    float* C = Cb + (size_t)blk * sC;

    float acc[4][8][4];
#pragma unroll
    for (int a = 0; a < 4; a++)
#pragma unroll
        for (int b = 0; b < 8; b++)
#pragma unroll
            for (int c = 0; c < 4; c++) acc[a][b][c] = 0.f;

    MMA256_CORE(A, B, K, M)

#pragma unroll
    for (int mf = 0; mf < 4; mf++) {
        const int r0 = m0 + wm * 64 + mf * 16 + (lane >> 2);
#pragma unroll
        for (int nf = 0; nf < 8; nf++) {
            const int col = n0 + wn * 64 + nf * 8 + (lane & 3) * 2;
            const float b0 = __ldg(&bias[col]), b1 = __ldg(&bias[col + 1]);
            if (r0 < M) {
                float2 v = make_float2(acc[mf][nf][0] + b0, acc[mf][nf][1] + b1);
                *(float2*)(C + (size_t)r0 * N + col) = v;
            }
            if (r0 + 8 < M) {
                float2 v = make_float2(acc[mf][nf][2] + b0, acc[mf][nf][3] + b1);
                *(float2*)(C + (size_t)(r0 + 8) * N + col) = v;
            }
        }
    }
}

// ---------------------------------------------------------------------------
// SIMT fp32 GEMM for KV projections (z-merged)
// ---------------------------------------------------------------------------
__global__ void __launch_bounds__(256, 2)
gemm_kv(const float* __restrict__ A,
        const float* __restrict__ Wk, const float* __restrict__ bk, float* __restrict__ Ck,
        const float* __restrict__ Wv, const float* __restrict__ bv, float* __restrict__ Cv,
        int M, int N, int K)
{
    const float* B    = blockIdx.z ? Wv : Wk;
    const float* bias = blockIdx.z ? bv : bk;
    float* C          = blockIdx.z ? Cv : Ck;

    const int BM = 128, BN = 128, BK = 16;
    __shared__ float As[BK][BM + 4];
    __shared__ float Bs[BK][BN + 4];

    const int tid  = threadIdx.x;
    const int tx   = tid & 15;
    const int ty   = tid >> 4;
    const int col0 = blockIdx.x * BN;

    float acc[8][8];
#pragma unroll
    for (int i = 0; i < 8; i++)
#pragma unroll
        for (int j = 0; j < 8; j++) acc[i][j] = 0.f;

    for (int k0 = 0; k0 < K; k0 += BK) {
#pragma unroll
        for (int it = 0; it < 2; it++) {
            int i = tid + 256 * it;
            int r = i >> 2, c4 = i & 3;
            float4 v = make_float4(0.f, 0.f, 0.f, 0.f);
            if (r < M) v = *(const float4*)(A + (size_t)r * K + k0 + c4 * 4);
            As[c4 * 4 + 0][r] = v.x; As[c4 * 4 + 1][r] = v.y;
            As[c4 * 4 + 2][r] = v.z; As[c4 * 4 + 3][r] = v.w;
        }
#pragma unroll
        for (int it = 0; it < 2; it++) {
            int i = tid + 256 * it;
            int r = i >> 2, c4 = i & 3;
            float4 v = *(const float4*)(B + (size_t)(col0 + r) * K + k0 + c4 * 4);
            Bs[c4 * 4 + 0][r] = v.x; Bs[c4 * 4 + 1][r] = v.y;
            Bs[c4 * 4 + 2][r] = v.z; Bs[c4 * 4 + 3][r] = v.w;
        }
        __syncthreads();
#pragma unroll
        for (int kk = 0; kk < BK; kk++) {
            float a[8], b[8];
#pragma unroll
            for (int i = 0; i < 8; i++) a[i] = As[kk][ty * 8 + i];
#pragma unroll
            for (int j = 0; j < 8; j++) b[j] = Bs[kk][tx * 8 + j];
#pragma unroll
            for (int i = 0; i < 8; i++)
#pragma unroll
                for (int j = 0; j < 8; j++)
                    acc[i][j] = fmaf(a[i], b[j], acc[i][j]);
        }
        __syncthreads();
    }
#pragma unroll
    for (int i = 0; i < 8; i++) {
        int r = ty * 8 + i;
        if (r >= M) continue;
#pragma unroll
        for (int j4 = 0; j4 < 2; j4++) {
            int c = col0 + tx * 8 + j4 * 4;
            float4 o;
            o.x = acc[i][j4 * 4 + 0] + bias[c + 0];
            o.y = acc[i][j4 * 4 + 1] + bias[c + 1];
            o.z = acc[i][j4 * 4 + 2] + bias[c + 2];
            o.w = acc[i][j4 * 4 + 3] + bias[c + 3];
            *(float4*)(C + (size_t)r * N + c) = o;
        }
    }
}

// ---------------------------------------------------------------------------
// VTg[blk][n][h*16+j] = sum_d v[blk*16+j, h*128+d] * Wo[n, h*128+d]
// ---------------------------------------------------------------------------
__global__ void __launch_bounds__(256, 2)
vproj_kernel(const float* __restrict__ V, const float* __restrict__ Wo,
             float* __restrict__ VTg)
{
    const int h  = blockIdx.y;
    const int n0 = blockIdx.x * 128;
    const int tid = threadIdx.x;
    const int tx = tid & 15;
    const int ty = tid >> 4;

    __shared__ float As[16][96 + 4];
    __shared__ float Bs[16][128 + 4];

    float acc[6][8];
#pragma unroll
    for (int i = 0; i < 6; i++)
#pragma unroll
        for (int j = 0; j < 8; j++) acc[i][j] = 0.f;

    for (int kc = 0; kc < 8; kc++) {
        const int kbase = h * HD + kc * 16;
#pragma unroll
        for (int it = 0; it < 2; it++) {
            int i = tid + 256 * it;
            if (i < 384) {
                int r = i >> 2, c4 = i & 3;
                float4 v = *(const float4*)(V + (size_t)r * DIMV + kbase + c4 * 4);
                As[c4 * 4 + 0][r] = v.x; As[c4 * 4 + 1][r] = v.y;
                As[c4 * 4 + 2][r] = v.z; As[c4 * 4 + 3][r] = v.w;
            }
        }
#pragma unroll
        for (int it = 0; it < 2; it++) {
            int i = tid + 256 * it;
            int r = i >> 2, c4 = i & 3;
            float4 v = *(const float4*)(Wo + (size_t)(n0 + r) * DIMV + kbase + c4 * 4);
            Bs[c4 * 4 + 0][r] = v.x; Bs[c4 * 4 + 1][r] = v.y;
            Bs[c4 * 4 + 2][r] = v.z; Bs[c4 * 4 + 3][r] = v.w;
        }
        __syncthreads();
#pragma unroll
        for (int kk = 0; kk < 16; kk++) {
            float a[6], b[8];
#pragma unroll
            for (int i = 0; i < 6; i++) a[i] = As[kk][ty * 6 + i];
#pragma unroll
            for (int j = 0; j < 8; j++) b[j] = Bs[kk][tx * 8 + j];
#pragma unroll
            for (int i = 0; i < 6; i++)
#pragma unroll
                for (int j = 0; j < 8; j++)
                    acc[i][j] = fmaf(a[i], b[j], acc[i][j]);
        }
        __syncthreads();
    }

#pragma unroll
    for (int i = 0; i < 6; i++) {
        const int jg = ty * 6 + i;
        float* dst = VTg + (size_t)(jg >> 4) * DIMV * NCOLS + h * NKV + (jg & 15);
#pragma unroll
        for (int j = 0; j < 8; j++)
            dst[(size_t)(n0 + tx * 8 + j) * NCOLS] = acc[i][j];
    }
}

// ---------------------------------------------------------------------------
// uproj: emits U3 split-3 (hi,hi,lo) directly, coalesced 48B uint4 stores.
// ---------------------------------------------------------------------------
__global__ void __launch_bounds__(256, 2)
uproj_kernel(const float* __restrict__ Kn, const float* __restrict__ Wq,
             const float* __restrict__ gq, __nv_bfloat16* __restrict__ U3)
{
    const int h  = blockIdx.y;
    const int m0 = blockIdx.x * 128;
    const int tid = threadIdx.x;
    const int tx = tid & 15;
    const int ty = tid >> 4;

    __shared__ float As[16][96 + 4];
    __shared__ float Bs[16][128 + 4];

    float acc[6][8];
#pragma unroll
    for (int i = 0; i < 6; i++)
#pragma unroll
        for (int j = 0; j < 8; j++) acc[i][j] = 0.f;

    for (int kc = 0; kc < 8; kc++) {
        const int kbase = h * HD + kc * 16;
#pragma unroll
        for (int it = 0; it < 2; it++) {
            int i = tid + 256 * it;
            if (i < 384) {
                int r = i >> 2, c4 = i & 3;
                float4 v = *(const float4*)(Kn + (size_t)r * DIMV + kbase + c4 * 4);
                float4 g = *(const float4*)(gq + kbase + c4 * 4);
                As[c4 * 4 + 0][r] = v.x * g.x; As[c4 * 4 + 1][r] = v.y * g.y;
                As[c4 * 4 + 2][r] = v.z * g.z; As[c4 * 4 + 3][r] = v.w * g.w;
            }
        }
#pragma unroll
        for (int it = 0; it < 2; it++) {
            int i = tid + 256 * it;
            int kr = i >> 5, c4 = i & 31;
            float4 v = *(const float4*)(Wq + (size_t)(kbase + kr) * DIMV + m0 + c4 * 4);
            Bs[kr][c4 * 4 + 0] = v.x; Bs[kr][c4 * 4 + 1] = v.y;
            Bs[kr][c4 * 4 + 2] = v.z; Bs[kr][c4 * 4 + 3] = v.w;
        }
        __syncthreads();
#pragma unroll
        for (int kk = 0; kk < 16; kk++) {
            float a[6], b[8];
#pragma unroll
            for (int i = 0; i < 6; i++) a[i] = As[kk][ty * 6 + i];
#pragma unroll
            for (int j = 0; j < 8; j++) b[j] = Bs[kk][tx * 8 + j];
#pragma unroll
            for (int i = 0; i < 6; i++)
#pragma unroll
                for (int j = 0; j < 8; j++)
                    acc[i][j] = fmaf(a[i], b[j], acc[i][j]);
        }
        __syncthreads();
    }

#pragma unroll
    for (int i = 0; i < 6; i++) {
        const int jg  = ty * 6 + i;
        const int row = (jg >> 4) * NCOLS + h * NKV + (jg & 15);
        union { __nv_bfloat16 hh[24]; uint4 u[3]; } o;
#pragma unroll
        for (int j = 0; j < 8; j++) {
            float f = acc[i][j];
            __nv_bfloat16 hi = __float2bfloat16(f);
            __nv_bfloat16 lo = __float2bfloat16(f - __bfloat162float(hi));
            o.hh[3*j] = hi; o.hh[3*j+1] = hi; o.hh[3*j+2] = lo;
        }
        uint4* dst = (uint4*)(U3 + (size_t)row * K2 + 3 * (m0 + tx * 8));
        dst[0] = o.u[0]; dst[1] = o.u[1]; dst[2] = o.u[2];
    }
}

__global__ void __launch_bounds__(256)
cb_kernel(const float* __restrict__ Kn, const float* __restrict__ bq,
          const float* __restrict__ gq, float* __restrict__ CB)
{
    int col = blockIdx.x * blockDim.x + threadIdx.x;
    if (col >= NUALL) return;
    int blk = col / NCOLS, rem = col % NCOLS;
    int h = rem >> 4, j = rem & 15;
    int jg = blk * NKV + j;
    const float* kp = Kn + (size_t)jg * DIMV + h * HD;
    const float* bp = bq + h * HD;
    const float* gp = gq + h * HD;
    float s = 0.f;
#pragma unroll 4
    for (int d = 0; d < HD; d++) s = fmaf(bp[d] * gp[d], kp[d], s);
    CB[col] = s;
}

// ---------------------------------------------------------------------------
// softmax: adds cb here (K-split GEMM omits it); emits P split-3 (hi,lo,hi)
// ---------------------------------------------------------------------------
__global__ void __launch_bounds__(256)
softmax_p3(const float* __restrict__ LG, const float* __restrict__ SS,
           const float* __restrict__ CB, __nv_bfloat16* __restrict__ P3)
{
    int gid = blockIdx.x * blockDim.x + threadIdx.x;
    if (gid >= L1V * NH) return;
    int t = gid / NH, h = gid % NH;
    const int blk = t / HWQ;
    const float s = rsqrtf(SS[t] * (1.0f / DIMV) + 1e-6f) * 0.08838834764831845f;
    const float* lp = LG + (size_t)t * NCOLS + h * NKV;
    const float* cp = CB + blk * NCOLS + h * NKV;
    float lg[NKV];
#pragma unroll
    for (int j4 = 0; j4 < 4; j4++) {
        float4 v = *(const float4*)(lp + j4 * 4);
        float4 c = *(const float4*)(cp + j4 * 4);
        lg[j4*4+0] = (v.x + c.x) * s; lg[j4*4+1] = (v.y + c.y) * s;
        lg[j4*4+2] = (v.z + c.z) * s; lg[j4*4+3] = (v.w + c.w) * s;
    }
    float m = lg[0];
#pragma unroll
    for (int j = 1; j < NKV; j++) m = fmaxf(m, lg[j]);
    float sum = 0.f;
#pragma unroll
    for (int j = 0; j < NKV; j++) { lg[j] = expf(lg[j] - m); sum += lg[j]; }
    const float inv = 1.f / sum;

    union { __nv_bfloat16 h48[48]; uint4 u[6]; } o;
#pragma unroll
    for (int j = 0; j < NKV; j++) {
        float p = lg[j] * inv;
        __nv_bfloat16 hi = __float2bfloat16(p);
        __nv_bfloat16 lo = __float2bfloat16(p - __bfloat162float(hi));
        o.h48[3*j] = hi; o.h48[3*j+1] = lo; o.h48[3*j+2] = hi;
    }
    uint4* dst = (uint4*)(P3 + (size_t)t * K3P + h * 48);
#pragma unroll
    for (int i = 0; i < 6; i++) dst[i] = o.u[i];
}

// ---------------------------------------------------------------------------
// rmsnorm (in-place) — K only
// ---------------------------------------------------------------------------
__global__ void __launch_bounds__(256)
rmsnorm_rows(float* __restrict__ X, const float* __restrict__ g)
{
    const int row = blockIdx.x;
    float* x = X + (size_t)row * DIMV;

    float ss = 0.f;
    for (int i = threadIdx.x; i < DIMV / 4; i += 256) {
        float4 v = ((const float4*)x)[i];
        ss += v.x * v.x + v.y * v.y + v.z * v.z + v.w * v.w;
    }
#pragma unroll
    for (int o = 16; o > 0; o >>= 1) ss += __shfl_xor_sync(~0u, ss, o);
    __shared__ float red[8];
    if ((threadIdx.x & 31) == 0) red[threadIdx.x >> 5] = ss;
    __syncthreads();
    if (threadIdx.x < 8) {
        float v = red[threadIdx.x];
#pragma unroll
        for (int o = 4; o > 0; o >>= 1) v += __shfl_xor_sync(0xffu, v, o);
        if (threadIdx.x == 0) red[0] = v;
    }
    __syncthreads();
    const float scale = rsqrtf(red[0] * (1.0f / DIMV) + 1e-6f);

    for (int i = threadIdx.x; i < DIMV / 4; i += 256) {
        float4 v  = ((const float4*)x)[i];
        float4 gg = ((const float4*)g)[i];
        v.x *= scale * gg.x; v.y *= scale * gg.y;
        v.z *= scale * gg.z; v.w *= scale * gg.w;
        ((float4*)x)[i] = v;
    }
}

// ---------------------------------------------------------------------------
// launch — round-11 schedule; ONLY change: K-split logits (atomic accumulate)
// ---------------------------------------------------------------------------
extern "C" void kernel_launch(void* const* d_in, const int* in_sizes, int n_in,
                              void* d_out, int out_size)
{
    (void)in_sizes; (void)n_in; (void)out_size;
    const float* x   = (const float*)d_in[0];
    const float* ctx = (const float*)d_in[1];
    const float* Wq = (const float*)d_in[6];
    const float* bq = (const float*)d_in[7];
    const float* Wk = (const float*)d_in[8];
    const float* bk = (const float*)d_in[9];
    const float* Wv = (const float*)d_in[10];
    const float* bv = (const float*)d_in[11];
    const float* Wo = (const float*)d_in[12];
    const float* bo = (const float*)d_in[13];
    const float* gq = (const float*)d_in[14];
    const float* gk = (const float*)d_in[15];
    float* out = (float*)d_out;

    float *kb, *vb, *vtg, *cb, *ssb, *lgb;
    __nv_bfloat16 *xb, *wb, *x3, *u3, *p3, *vt3;
    cudaGetSymbolAddress((void**)&kb,  g_k);
    cudaGetSymbolAddress((void**)&vb,  g_v);
    cudaGetSymbolAddress((void**)&vtg, g_vtg);
    cudaGetSymbolAddress((void**)&cb,  g_cb);
    cudaGetSymbolAddress((void**)&ssb, g_ss);
    cudaGetSymbolAddress((void**)&lgb, g_lg);
    cudaGetSymbolAddress((void**)&xb,  g_xb);
    cudaGetSymbolAddress((void**)&wb,  g_wb);
    cudaGetSymbolAddress((void**)&x3,  g_x3);
    cudaGetSymbolAddress((void**)&u3,  g_u3);
    cudaGetSymbolAddress((void**)&p3,  g_p3);
    cudaGetSymbolAddress((void**)&vt3, g_vt3);

    const int dynsmem  = STG * STAGEB;
    const int dynsmem2 = STG2 * STAGE2B;

    static cudaStream_t sB = nullptr;
    static cudaEvent_t  e0 = nullptr, eW = nullptr, eB = nullptr;
    if (sB == nullptr) {
        cudaStreamCreateWithFlags(&sB, cudaStreamNonBlocking);
        cudaEventCreateWithFlags(&e0, cudaEventDisableTiming);
        cudaEventCreateWithFlags(&eW, cudaEventDisableTiming);
        cudaEventCreateWithFlags(&eB, cudaEventDisableTiming);
        cudaFuncSetAttribute(mma_logits_ks, cudaFuncAttributeMaxDynamicSharedMemorySize, dynsmem);
        cudaFuncSetAttribute(mma256_ss, cudaFuncAttributeMaxDynamicSharedMemorySize, dynsmem2);
        cudaFuncSetAttribute(mma256_z,  cudaFuncAttributeMaxDynamicSharedMemorySize, dynsmem2);
    }

    // fork
    cudaEventRecord(e0, 0);
    cudaStreamWaitEvent(sB, e0, 0);

    // side stream B: zeros + Wq->bf16 first (norm GEMM waits on eW),
    // then the KV prep chain (uproj emits u3 directly).
    zero_f32<<<1024, 256, 0, sB>>>(ssb, L1V / 4);
    zero_f32<<<2048, 256, 0, sB>>>(lgb, (size_t)L1V * NCOLS / 4);
    cvt_bf16<<<2048, 256, 0, sB>>>(Wq, wb, (size_t)DIMV * DIMV / 8);
    cudaEventRecord(eW, sB);
    {
        dim3 grid(DIMV / 128, 1, 2);
        gemm_kv<<<grid, 256, 0, sB>>>(ctx, Wk, bk, kb, Wv, bv, vb, LAV, DIMV, KVDIM);
    }
    rmsnorm_rows<<<LAV, 256, 0, sB>>>(kb, gk);
    {
        dim3 grid(DIMV / 128, NH);
        vproj_kernel<<<grid, 256, 0, sB>>>(vb, Wo, vtg);
        uproj_kernel<<<grid, 256, 0, sB>>>(kb, Wq, gq, u3);
    }
    cb_kernel<<<(NUALL + 255) / 256, 256, 0, sB>>>(kb, bq, gq, cb);
    cvt_split3<1><<<2048, 256, 0, sB>>>(vtg, vt3, (size_t)NBLK * DIMV * NCOLS / 8);
    cudaEventRecord(eB, sB);

    // main: x conversion + norm GEMM (side chain hides underneath)
    cvt_x_fused<<<2048, 256>>>(x, xb, x3, (size_t)L1V * DIMV / 8);
    cudaStreamWaitEvent(0, eW, 0);
    {
        dim3 grid(DIMV / 256, (L1V + 127) / 128);
        mma256_ss<<<grid, 256, dynsmem2>>>(xb, wb, bq, ssb, L1V, DIMV, DIMV);
    }

    // join, then K-split logits -> softmax(+cb) -> P@VT
    cudaStreamWaitEvent(0, eB, 0);
    {
        dim3 grid(NCOLS / 128, (HWQ + 127) / 128, NBLK * NKSPL);
        mma_logits_ks<<<grid, 256, dynsmem>>>(x3, u3, lgb);
    }
    softmax_p3<<<(L1V * NH + 255) / 256, 256>>>(lgb, ssb, cb, p3);
    {
        dim3 grid(DIMV / 256, (HWQ + 127) / 128, NBLK);
        mma256_z<<<grid, 256, dynsmem2>>>(
            p3, vt3, bo, out, HWQ, DIMV, K3P,
            (size_t)HWQ * K3P, (size_t)DIMV * K3P, (size_t)HWQ * DIMV);
    }
}

// round 16
// speedup vs baseline: 1.7387x; 1.1007x over previous
#include <cuda_runtime.h>
#include <cuda_bf16.h>
#include <cuda_fp8.h>
#include <math.h>
#include <stdint.h>

#define DIMV   5120
#define KVDIM  1536
#define NH     40
#define HD     128
#define L1V    9360
#define LAV    96
#define NBLK   6
#define NKV    16
#define HWQ    1560
#define K2     (3 * DIMV)
#define NCOLS  (NH * NKV)
#define K3P    (3 * NCOLS)
#define NUALL  (NBLK * NCOLS)
#define NKSPL  3
#define SXW2   262144.0f      // (8*64)^2 scale for fp8 norm GEMM

// ---------------- scratch ----------------------------------------------------
__device__ float g_k[(size_t)LAV * DIMV];
__device__ float g_v[(size_t)LAV * DIMV];
__device__ float g_vtg[(size_t)NBLK * DIMV * NCOLS];
__device__ float g_cb[NUALL];
__device__ float g_ss[L1V];
__device__ float g_lg[(size_t)L1V * NCOLS];
__device__ uint8_t g_x8[(size_t)L1V * DIMV];   // x scaled by 8, e4m3
__device__ uint8_t g_w8[(size_t)DIMV * DIMV];  // Wq scaled by 64, e4m3
__device__ __nv_bfloat16 g_x3[(size_t)L1V * K2];
__device__ __nv_bfloat16 g_u3[(size_t)NUALL * K2];
__device__ __nv_bfloat16 g_p3[(size_t)L1V * K3P];
__device__ __nv_bfloat16 g_vt3[(size_t)NBLK * DIMV * K3P];

// ---------------- helpers ----------------------------------------------------
__device__ __forceinline__ uint32_t smem_u32(const void* p) {
    uint32_t a;
    asm("{ .reg .u64 t; cvta.to.shared.u64 t, %1; cvt.u32.u64 %0, t; }" : "=r"(a) : "l"(p));
    return a;
}
__device__ __forceinline__ void cp16(uint32_t dst, const void* src, int srcsize) {
    asm volatile("cp.async.cg.shared.global [%0], [%1], 16, %2;"
                 :: "r"(dst), "l"(src), "r"(srcsize) : "memory");
}
__device__ __forceinline__ uint8_t f2e4m3(float f) {
    __nv_fp8_e4m3 q(f);
    return *(uint8_t*)&q;
}

// ---------------------------------------------------------------------------
// converters
// ---------------------------------------------------------------------------
// x -> split3 bf16 (hi,lo,hi) AND e4m3 (x*8)
__global__ void __launch_bounds__(256)
cvt_x_fused(const float* __restrict__ X, uint8_t* __restrict__ X8,
            __nv_bfloat16* __restrict__ X3, size_t n8)
{
    size_t i = (size_t)blockIdx.x * blockDim.x + threadIdx.x;
    const size_t stride = (size_t)gridDim.x * blockDim.x;
    for (; i < n8; i += stride) {
        const float4* src = (const float4*)X + i * 2;
        float4 v0 = src[0], v1 = src[1];
        float f[8] = {v0.x, v0.y, v0.z, v0.w, v1.x, v1.y, v1.z, v1.w};
        union { uint8_t b[8]; uint2 u; } o8;
        union { __nv_bfloat16 h[24]; uint4 u[3]; } o3;
#pragma unroll
        for (int j = 0; j < 8; j++) {
            __nv_bfloat16 hi = __float2bfloat16(f[j]);
            __nv_bfloat16 lo = __float2bfloat16(f[j] - __bfloat162float(hi));
            o3.h[3*j] = hi; o3.h[3*j+1] = lo; o3.h[3*j+2] = hi;
            o8.b[j] = f2e4m3(f[j] * 8.0f);
        }
        ((uint2*)X8)[i] = o8.u;
        uint4* dst = (uint4*)(X3 + i * 24);
        dst[0] = o3.u[0]; dst[1] = o3.u[1]; dst[2] = o3.u[2];
    }
}

// Wq -> e4m3 (w*64)
__global__ void __launch_bounds__(256)
cvt_w8(const float* __restrict__ X, uint8_t* __restrict__ Y, size_t n8)
{
    size_t i = (size_t)blockIdx.x * blockDim.x + threadIdx.x;
    const size_t stride = (size_t)gridDim.x * blockDim.x;
    for (; i < n8; i += stride) {
        const float4* src = (const float4*)X + i * 2;
        float4 v0 = src[0], v1 = src[1];
        float f[8] = {v0.x, v0.y, v0.z, v0.w, v1.x, v1.y, v1.z, v1.w};
        union { uint8_t b[8]; uint2 u; } o;
#pragma unroll
        for (int j = 0; j < 8; j++) o.b[j] = f2e4m3(f[j] * 64.0f);
        ((uint2*)Y)[i] = o.u;
    }
}

template <int PAT>
__global__ void __launch_bounds__(256)
cvt_split3(const float* __restrict__ X, __nv_bfloat16* __restrict__ Y, size_t n8)
{
    size_t i = (size_t)blockIdx.x * blockDim.x + threadIdx.x;
    const size_t stride = (size_t)gridDim.x * blockDim.x;
    for (; i < n8; i += stride) {
        const float4* src = (const float4*)X + i * 2;
        float4 v0 = src[0], v1 = src[1];
        float f[8] = {v0.x, v0.y, v0.z, v0.w, v1.x, v1.y, v1.z, v1.w};
        union { __nv_bfloat16 h[24]; uint4 u[3]; } o;
#pragma unroll
        for (int j = 0; j < 8; j++) {
            __nv_bfloat16 hi = __float2bfloat16(f[j]);
            __nv_bfloat16 lo = __float2bfloat16(f[j] - __bfloat162float(hi));
            if (PAT == 0) { o.h[3*j] = hi; o.h[3*j+1] = lo; o.h[3*j+2] = hi; }
            else          { o.h[3*j] = hi; o.h[3*j+1] = hi; o.h[3*j+2] = lo; }
        }
        uint4* dst = (uint4*)(Y + i * 24);
        dst[0] = o.u[0]; dst[1] = o.u[1]; dst[2] = o.u[2];
    }
}

__global__ void __launch_bounds__(256)
zero_f32(float* __restrict__ p, size_t n4)
{
    size_t i = (size_t)blockIdx.x * blockDim.x + threadIdx.x;
    const size_t stride = (size_t)gridDim.x * blockDim.x;
    for (; i < n4; i += stride)
        ((float4*)p)[i] = make_float4(0.f, 0.f, 0.f, 0.f);
}

// ---------------------------------------------------------------------------
// 128x128 HMMA, K-split logits GEMM (round-15 winner)
// ---------------------------------------------------------------------------
#define BMg 128
#define BKg 32
#define STG 3
#define ROWB  80
#define TILEB (BMg * ROWB)
#define STAGEB (2 * TILEB)

__global__ void __launch_bounds__(256, 2)
mma_logits_ks(const __nv_bfloat16* __restrict__ X3, const __nv_bfloat16* __restrict__ U3,
              float* __restrict__ LG)
{
    extern __shared__ char ds[];
    const uint32_t base = smem_u32(ds);
    const int tid  = threadIdx.x;
    const int lane = tid & 31;
    const int warp = tid >> 5;
    const int wm   = warp & 3;
    const int wn   = warp >> 2;
    const int blk  = blockIdx.z / NKSPL;
    const int kc   = blockIdx.z % NKSPL;
    const int m0 = blockIdx.y * BMg, n0 = blockIdx.x * BMg;

    const __nv_bfloat16* A = X3 + (size_t)blk * HWQ * K2 + (size_t)kc * DIMV;
    const __nv_bfloat16* B = U3 + (size_t)blk * NCOLS * K2 + (size_t)kc * DIMV;

    float acc[2][8][4];
#pragma unroll
    for (int a = 0; a < 2; a++)
#pragma unroll
        for (int b = 0; b < 8; b++)
#pragma unroll
            for (int c = 0; c < 4; c++) acc[a][b][c] = 0.f;

    const int lrow = tid >> 1;
    const int lc   = (tid & 1) * 2;
    auto load_stage = [&](int s, int k0) {
        const uint32_t sa = base + (uint32_t)s * STAGEB;
        const uint32_t sb = sa + TILEB;
        const __nv_bfloat16* ga = A + (size_t)(m0 + lrow) * K2 + k0 + lc * 8;
        const int pa = (m0 + lrow) < HWQ ? 16 : 0;
        cp16(sa + lrow * ROWB + lc * 16,       ga,     pa);
        cp16(sa + lrow * ROWB + (lc + 1) * 16, ga + 8, pa);
        const __nv_bfloat16* gb = B + (size_t)(n0 + lrow) * K2 + k0 + lc * 8;
        cp16(sb + lrow * ROWB + lc * 16,       gb,     16);
        cp16(sb + lrow * ROWB + (lc + 1) * 16, gb + 8, 16);
    };
    const int niter = DIMV / BKg;
#pragma unroll
    for (int s = 0; s < STG - 1; s++) {
        load_stage(s, s * BKg);
        asm volatile("cp.async.commit_group;" ::: "memory");
    }
    for (int it = 0; it < niter; it++) {
        asm volatile("cp.async.wait_group %0;" :: "n"(STG - 2) : "memory");
        __syncthreads();
        const int pf = it + STG - 1;
        if (pf < niter) load_stage(pf % STG, pf * BKg);
        asm volatile("cp.async.commit_group;" ::: "memory");
        const uint32_t sa = base + (uint32_t)(it % STG) * STAGEB;
        const uint32_t sb = sa + TILEB;
#pragma unroll
        for (int h = 0; h < 2; h++) {
            uint32_t a[2][4], b4[4][4];
            const int koff = (h * 16 + ((lane >> 4) * 8)) * 2;
#pragma unroll
            for (int mf = 0; mf < 2; mf++) {
                uint32_t addr = sa + (wm * 32 + mf * 16 + (lane & 15)) * ROWB + koff;
                asm volatile("ldmatrix.sync.aligned.m8n8.x4.shared.b16 {%0,%1,%2,%3}, [%4];"
                             : "=r"(a[mf][0]), "=r"(a[mf][1]), "=r"(a[mf][2]), "=r"(a[mf][3])
                             : "r"(addr));
            }
#pragma unroll
            for (int nb = 0; nb < 4; nb++) {
                uint32_t addr = sb + (wn * 64 + nb * 16 + (lane & 15)) * ROWB + koff;
                asm volatile("ldmatrix.sync.aligned.m8n8.x4.shared.b16 {%0,%1,%2,%3}, [%4];"
                             : "=r"(b4[nb][0]), "=r"(b4[nb][1]), "=r"(b4[nb][2]), "=r"(b4[nb][3])
                             : "r"(addr));
            }
#pragma unroll
            for (int mf = 0; mf < 2; mf++) {
#pragma unroll
                for (int nf = 0; nf < 8; nf++) {
                    const uint32_t bb0 = (nf & 1) ? b4[nf >> 1][1] : b4[nf >> 1][0];
                    const uint32_t bb1 = (nf & 1) ? b4[nf >> 1][3] : b4[nf >> 1][2];
                    asm volatile(
                        "mma.sync.aligned.m16n8k16.row.col.f32.bf16.bf16.f32 "
                        "{%0,%1,%2,%3}, {%4,%5,%6,%7}, {%8,%9}, {%0,%1,%2,%3};"
                        : "+f"(acc[mf][nf][0]), "+f"(acc[mf][nf][1]),
                          "+f"(acc[mf][nf][2]), "+f"(acc[mf][nf][3])
                        : "r"(a[mf][0]), "r"(a[mf][1]), "r"(a[mf][2]), "r"(a[mf][3]),
                          "r"(bb0), "r"(bb1));
                }
            }
        }
    }
    asm volatile("cp.async.wait_group 0;" ::: "memory");

    float* Cb = LG + (size_t)blk * HWQ * NCOLS;
#pragma unroll
    for (int mf = 0; mf < 2; mf++) {
        const int r0 = m0 + wm * 32 + mf * 16 + (lane >> 2);
#pragma unroll
        for (int nf = 0; nf < 8; nf++) {
            const int col = n0 + wn * 64 + nf * 8 + (lane & 3) * 2;
            if (r0 < HWQ) {
                atomicAdd(Cb + (size_t)r0 * NCOLS + col,     acc[mf][nf][0]);
                atomicAdd(Cb + (size_t)r0 * NCOLS + col + 1, acc[mf][nf][1]);
            }
            if (r0 + 8 < HWQ) {
                atomicAdd(Cb + (size_t)(r0 + 8) * NCOLS + col,     acc[mf][nf][2]);
                atomicAdd(Cb + (size_t)(r0 + 8) * NCOLS + col + 1, acc[mf][nf][3]);
            }
        }
    }
}

// ---------------------------------------------------------------------------
// 128x256 e4m3 fp8 norm GEMM: ss[t] += rowsum over N of (512*y)^2.
// Fragment byte-layout of m16n8k32 e4m3 == m16n8k16 f16 (2 fp8 per b16 slot),
// so the ldmatrix plumbing is identical; only pointers/K-step/mma change.
// Per stage: 64 bytes (=64 e4m3) per row; 2 k32-mma windows of 32B each.
// ---------------------------------------------------------------------------
#define A2B    10240
#define STAGE2B 30720
#define STG2   3

__global__ void __launch_bounds__(256, 1)
mma256_ss8(const uint8_t* __restrict__ A, const uint8_t* __restrict__ B,
           const float* __restrict__ bias, float* __restrict__ SS,
           int M, int N, int K)
{
    extern __shared__ char ds[];
    const uint32_t base = smem_u32(ds);
    const int tid  = threadIdx.x;
    const int lane = tid & 31;
    const int warp = tid >> 5;
    const int wm   = warp & 1;
    const int wn   = warp >> 1;
    const int m0 = blockIdx.y * 128, n0 = blockIdx.x * 256;

    float acc[4][8][4];
#pragma unroll
    for (int a = 0; a < 4; a++)
#pragma unroll
        for (int b = 0; b < 8; b++)
#pragma unroll
            for (int c = 0; c < 4; c++) acc[a][b][c] = 0.f;

    auto load_stage = [&](int s, int k0) {   // k0 in bytes (= elements)
        const uint32_t sa = base + (uint32_t)s * STAGE2B;
        const uint32_t sb = sa + A2B;
#pragma unroll
        for (int it2 = 0; it2 < 6; it2++) {
            int idx = tid + 256 * it2;
            int row = idx >> 2, c = idx & 3;
            if (row < 128) {
                const uint8_t* g = A + (size_t)(m0 + row) * K + k0 + c * 16;
                cp16(sa + row * 80 + c * 16, g, (m0 + row) < M ? 16 : 0);
            } else {
                int br = row - 128;
                const uint8_t* g = B + (size_t)(n0 + br) * K + k0 + c * 16;
                cp16(sb + br * 80 + c * 16, g, 16);
            }
        }
    };
    const int niter = K / 64;   // 80
#pragma unroll
    for (int s = 0; s < STG2 - 1; s++) {
        load_stage(s, s * 64);
        asm volatile("cp.async.commit_group;" ::: "memory");
    }
    for (int it = 0; it < niter; it++) {
        asm volatile("cp.async.wait_group %0;" :: "n"(STG2 - 2) : "memory");
        __syncthreads();
        const int pf = it + STG2 - 1;
        if (pf < niter) load_stage(pf % STG2, pf * 64);
        asm volatile("cp.async.commit_group;" ::: "memory");
        const uint32_t sa = base + (uint32_t)(it % STG2) * STAGE2B;
        const uint32_t sb = sa + A2B;
#pragma unroll
        for (int h = 0; h < 2; h++) {
            uint32_t a4[4][4], b4[4][4];
            const int koff = h * 32 + ((lane >> 4) * 16);   // bytes
#pragma unroll
            for (int mf = 0; mf < 4; mf++) {
                uint32_t addr = sa + (wm * 64 + mf * 16 + (lane & 15)) * 80 + koff;
                asm volatile("ldmatrix.sync.aligned.m8n8.x4.shared.b16 {%0,%1,%2,%3}, [%4];"
                             : "=r"(a4[mf][0]), "=r"(a4[mf][1]), "=r"(a4[mf][2]), "=r"(a4[mf][3])
                             : "r"(addr));
            }
#pragma unroll
            for (int nb = 0; nb < 4; nb++) {
                uint32_t addr = sb + (wn * 64 + nb * 16 + (lane & 15)) * 80 + koff;
                asm volatile("ldmatrix.sync.aligned.m8n8.x4.shared.b16 {%0,%1,%2,%3}, [%4];"
                             : "=r"(b4[nb][0]), "=r"(b4[nb][1]), "=r"(b4[nb][2]), "=r"(b4[nb][3])
                             : "r"(addr));
            }
#pragma unroll
            for (int mf = 0; mf < 4; mf++) {
#pragma unroll
                for (int nf = 0; nf < 8; nf++) {
                    const uint32_t bb0 = (nf & 1) ? b4[nf >> 1][1] : b4[nf >> 1][0];
                    const uint32_t bb1 = (nf & 1) ? b4[nf >> 1][3] : b4[nf >> 1][2];
                    asm volatile(
                        "mma.sync.aligned.m16n8k32.row.col.f32.e4m3.e4m3.f32 "
                        "{%0,%1,%2,%3}, {%4,%5,%6,%7}, {%8,%9}, {%0,%1,%2,%3};"
                        : "+f"(acc[mf][nf][0]), "+f"(acc[mf][nf][1]),
                          "+f"(acc[mf][nf][2]), "+f"(acc[mf][nf][3])
                        : "r"(a4[mf][0]), "r"(a4[mf][1]), "r"(a4[mf][2]), "r"(a4[mf][3]),
                          "r"(bb0), "r"(bb1));
                }
            }
        }
    }
    asm volatile("cp.async.wait_group 0;" ::: "memory");

    // epilogue: v = acc + 512*b; SS += v^2 (scaled domain)
#pragma unroll
    for (int mf = 0; mf < 4; mf++) {
        const int r0 = m0 + wm * 64 + mf * 16 + (lane >> 2);
        float s0 = 0.f, s1 = 0.f;
#pragma unroll
        for (int nf = 0; nf < 8; nf++) {
            const int col = n0 + wn * 64 + nf * 8 + (lane & 3) * 2;
            const float b0 = __ldg(&bias[col]) * 512.f, b1 = __ldg(&bias[col + 1]) * 512.f;
            float v0 = acc[mf][nf][0] + b0, v1 = acc[mf][nf][1] + b1;
            float v2 = acc[mf][nf][2] + b0, v3 = acc[mf][nf][3] + b1;
            s0 += v0 * v0 + v1 * v1;
            s1 += v2 * v2 + v3 * v3;
        }
        s0 += __shfl_xor_sync(~0u, s0, 1); s0 += __shfl_xor_sync(~0u, s0, 2);
        s1 += __shfl_xor_sync(~0u, s1, 1); s1 += __shfl_xor_sync(~0u, s1, 2);
        if ((lane & 3) == 0) {
            if (r0 < M)     atomicAdd(&SS[r0], s0);
            if (r0 + 8 < M) atomicAdd(&SS[r0 + 8], s1);
        }
    }
}

// ---------------------------------------------------------------------------
// 128x256 bf16 HMMA (P@VT)
// ---------------------------------------------------------------------------
#define MMA256_CORE(A_, B_, Kdim_, Mbound_)                                           \
    auto load_stage = [&](int s, int k0) {                                            \
        const uint32_t sa = base + (uint32_t)s * STAGE2B;                             \
        const uint32_t sb = sa + A2B;                                                 \
        _Pragma("unroll")                                                             \
        for (int it2 = 0; it2 < 6; it2++) {                                           \
            int idx = tid + 256 * it2;                                                \
            int row = idx >> 2, c = idx & 3;                                          \
            if (row < 128) {                                                          \
                const __nv_bfloat16* g = A_ + (size_t)(m0 + row) * Kdim_ + k0 + c * 8;\
                cp16(sa + row * 80 + c * 16, g, (m0 + row) < Mbound_ ? 16 : 0);       \
            } else {                                                                  \
                int br = row - 128;                                                   \
                const __nv_bfloat16* g = B_ + (size_t)(n0 + br) * Kdim_ + k0 + c * 8; \
                cp16(sb + br * 80 + c * 16, g, 16);                                   \
            }                                                                         \
        }                                                                             \
    };                                                                                \
    const int niter = Kdim_ / 32;                                                     \
    _Pragma("unroll")                                                                 \
    for (int s = 0; s < STG2 - 1; s++) {                                              \
        load_stage(s, s * 32);                                                        \
        asm volatile("cp.async.commit_group;" ::: "memory");                          \
    }                                                                                 \
    for (int it = 0; it < niter; it++) {                                              \
        asm volatile("cp.async.wait_group %0;" :: "n"(STG2 - 2) : "memory");          \
        __syncthreads();                                                              \
        const int pf = it + STG2 - 1;                                                 \
        if (pf < niter) load_stage(pf % STG2, pf * 32);                               \
        asm volatile("cp.async.commit_group;" ::: "memory");                          \
        const uint32_t sa = base + (uint32_t)(it % STG2) * STAGE2B;                   \
        const uint32_t sb = sa + A2B;                                                 \
        _Pragma("unroll")                                                             \
        for (int h = 0; h < 2; h++) {                                                 \
            uint32_t a4[4][4], b4[4][4];                                              \
            const int koff = (h * 16 + ((lane >> 4) * 8)) * 2;                        \
            _Pragma("unroll")                                                         \
            for (int mf = 0; mf < 4; mf++) {                                          \
                uint32_t addr = sa + (wm * 64 + mf * 16 + (lane & 15)) * 80 + koff;   \
                asm volatile("ldmatrix.sync.aligned.m8n8.x4.shared.b16 {%0,%1,%2,%3}, [%4];" \
                             : "=r"(a4[mf][0]), "=r"(a4[mf][1]), "=r"(a4[mf][2]), "=r"(a4[mf][3]) \
                             : "r"(addr));                                            \
            }                                                                         \
            _Pragma("unroll")                                                         \
            for (int nb = 0; nb < 4; nb++) {                                          \
                uint32_t addr = sb + (wn * 64 + nb * 16 + (lane & 15)) * 80 + koff;   \
                asm volatile("ldmatrix.sync.aligned.m8n8.x4.shared.b16 {%0,%1,%2,%3}, [%4];" \
                             : "=r"(b4[nb][0]), "=r"(b4[nb][1]), "=r"(b4[nb][2]), "=r"(b4[nb][3]) \
                             : "r"(addr));                                            \
            }                                                                         \
            _Pragma("unroll")                                                         \
            for (int mf = 0; mf < 4; mf++) {                                          \
                _Pragma("unroll")                                                     \
                for (int nf = 0; nf < 8; nf++) {                                      \
                    const uint32_t bb0 = (nf & 1) ? b4[nf >> 1][1] : b4[nf >> 1][0];  \
                    const uint32_t bb1 = (nf & 1) ? b4[nf >> 1][3] : b4[nf >> 1][2];  \
                    asm volatile(                                                     \
                        "mma.sync.aligned.m16n8k16.row.col.f32.bf16.bf16.f32 "        \
                        "{%0,%1,%2,%3}, {%4,%5,%6,%7}, {%8,%9}, {%0,%1,%2,%3};"       \
                        : "+f"(acc[mf][nf][0]), "+f"(acc[mf][nf][1]),                 \
                          "+f"(acc[mf][nf][2]), "+f"(acc[mf][nf][3])                  \
                        : "r"(a4[mf][0]), "r"(a4[mf][1]), "r"(a4[mf][2]), "r"(a4[mf][3]), \
                          "r"(bb0), "r"(bb1));                                        \
                }                                                                     \
            }                                                                         \
        }                                                                             \
    }                                                                                 \
    asm volatile("cp.async.wait_group 0;" ::: "memory");

__global__ void __launch_bounds__(256, 1)
mma256_z(const __nv_bfloat16* __restrict__ Ab, const __nv_bfloat16* __restrict__ Bb,
         const float* __restrict__ bias, float* __restrict__ Cb,
         int M, int N, int K, size_t sA, size_t sB, size_t sC)
{
    extern __shared__ char ds[];
    const uint32_t base = smem_u32(ds);
    const int tid  = threadIdx.x;
    const int lane = tid & 31;
    const int warp = tid >> 5;
    const int wm   = warp & 1;
    const int wn   = warp >> 1;
    const int blk  = blockIdx.z;
    const int m0 = blockIdx.y * 128, n0 = blockIdx.x * 256;

    const __nv_bfloat16* A = Ab + (size_t)blk * sA;
    const __nv_bfloat16* B = Bb + (size_t)blk * sB;
    float* C = Cb + (size_t)blk * sC;

    float acc[4][8][4];
#pragma unroll
    for (int a = 0; a < 4; a++)
#pragma unroll
        for (int b = 0; b < 8; b++)
#pragma unroll
            for (int c = 0; c < 4; c++) acc[a][b][c] = 0.f;

    MMA256_CORE(A, B, K, M)

#pragma unroll
    for (int mf = 0; mf < 4; mf++) {
        const int r0 = m0 + wm * 64 + mf * 16 + (lane >> 2);
#pragma unroll
        for (int nf = 0; nf < 8; nf++) {
            const int col = n0 + wn * 64 + nf * 8 + (lane & 3) * 2;
            const float b0 = __ldg(&bias[col]), b1 = __ldg(&bias[col + 1]);
            if (r0 < M) {
                float2 v = make_float2(acc[mf][nf][0] + b0, acc[mf][nf][1] + b1);
                *(float2*)(C + (size_t)r0 * N + col) = v;
            }
            if (r0 + 8 < M) {
                float2 v = make_float2(acc[mf][nf][2] + b0, acc[mf][nf][3] + b1);
                *(float2*)(C + (size_t)(r0 + 8) * N + col) = v;
            }
        }
    }
}

// ---------------------------------------------------------------------------
// SIMT fp32 GEMM for KV projections (z-merged)
// ---------------------------------------------------------------------------
__global__ void __launch_bounds__(256, 2)
gemm_kv(const float* __restrict__ A,
        const float* __restrict__ Wk, const float* __restrict__ bk, float* __restrict__ Ck,
        const float* __restrict__ Wv, const float* __restrict__ bv, float* __restrict__ Cv,
        int M, int N, int K)
{
    const float* B    = blockIdx.z ? Wv : Wk;
    const float* bias = blockIdx.z ? bv : bk;
    float* C          = blockIdx.z ? Cv : Ck;

    const int BM = 128, BN = 128, BK = 16;
    __shared__ float As[BK][BM + 4];
    __shared__ float Bs[BK][BN + 4];

    const int tid  = threadIdx.x;
    const int tx   = tid & 15;
    const int ty   = tid >> 4;
    const int col0 = blockIdx.x * BN;

    float acc[8][8];
#pragma unroll
    for (int i = 0; i < 8; i++)
#pragma unroll
        for (int j = 0; j < 8; j++) acc[i][j] = 0.f;

    for (int k0 = 0; k0 < K; k0 += BK) {
#pragma unroll
        for (int it = 0; it < 2; it++) {
            int i = tid + 256 * it;
            int r = i >> 2, c4 = i & 3;
            float4 v = make_float4(0.f, 0.f, 0.f, 0.f);
            if (r < M) v = *(const float4*)(A + (size_t)r * K + k0 + c4 * 4);
            As[c4 * 4 + 0][r] = v.x; As[c4 * 4 + 1][r] = v.y;
            As[c4 * 4 + 2][r] = v.z; As[c4 * 4 + 3][r] = v.w;
        }
#pragma unroll
        for (int it = 0; it < 2; it++) {
            int i = tid + 256 * it;
            int r = i >> 2, c4 = i & 3;
            float4 v = *(const float4*)(B + (size_t)(col0 + r) * K + k0 + c4 * 4);
            Bs[c4 * 4 + 0][r] = v.x; Bs[c4 * 4 + 1][r] = v.y;
            Bs[c4 * 4 + 2][r] = v.z; Bs[c4 * 4 + 3][r] = v.w;
        }
        __syncthreads();
#pragma unroll
        for (int kk = 0; kk < BK; kk++) {
            float a[8], b[8];
#pragma unroll
            for (int i = 0; i < 8; i++) a[i] = As[kk][ty * 8 + i];
#pragma unroll
            for (int j = 0; j < 8; j++) b[j] = Bs[kk][tx * 8 + j];
#pragma unroll
            for (int i = 0; i < 8; i++)
#pragma unroll
                for (int j = 0; j < 8; j++)
                    acc[i][j] = fmaf(a[i], b[j], acc[i][j]);
        }
        __syncthreads();
    }
#pragma unroll
    for (int i = 0; i < 8; i++) {
        int r = ty * 8 + i;
        if (r >= M) continue;
#pragma unroll
        for (int j4 = 0; j4 < 2; j4++) {
            int c = col0 + tx * 8 + j4 * 4;
            float4 o;
            o.x = acc[i][j4 * 4 + 0] + bias[c + 0];
            o.y = acc[i][j4 * 4 + 1] + bias[c + 1];
            o.z = acc[i][j4 * 4 + 2] + bias[c + 2];
            o.w = acc[i][j4 * 4 + 3] + bias[c + 3];
            *(float4*)(C + (size_t)r * N + c) = o;
        }
    }
}

// ---------------------------------------------------------------------------
// VTg[blk][n][h*16+j] = sum_d v[blk*16+j, h*128+d] * Wo[n, h*128+d]
// ---------------------------------------------------------------------------
__global__ void __launch_bounds__(256, 2)
vproj_kernel(const float* __restrict__ V, const float* __restrict__ Wo,
             float* __restrict__ VTg)
{
    const int h  = blockIdx.y;
    const int n0 = blockIdx.x * 128;
    const int tid = threadIdx.x;
    const int tx = tid & 15;
    const int ty = tid >> 4;

    __shared__ float As[16][96 + 4];
    __shared__ float Bs[16][128 + 4];

    float acc[6][8];
#pragma unroll
    for (int i = 0; i < 6; i++)
#pragma unroll
        for (int j = 0; j < 8; j++) acc[i][j] = 0.f;

    for (int kc = 0; kc < 8; kc++) {
        const int kbase = h * HD + kc * 16;
#pragma unroll
        for (int it = 0; it < 2; it++) {
            int i = tid + 256 * it;
            if (i < 384) {
                int r = i >> 2, c4 = i & 3;
                float4 v = *(const float4*)(V + (size_t)r * DIMV + kbase + c4 * 4);
                As[c4 * 4 + 0][r] = v.x; As[c4 * 4 + 1][r] = v.y;
                As[c4 * 4 + 2][r] = v.z; As[c4 * 4 + 3][r] = v.w;
            }
        }
#pragma unroll
        for (int it = 0; it < 2; it++) {
            int i = tid + 256 * it;
            int r = i >> 2, c4 = i & 3;
            float4 v = *(const float4*)(Wo + (size_t)(n0 + r) * DIMV + kbase + c4 * 4);
            Bs[c4 * 4 + 0][r] = v.x; Bs[c4 * 4 + 1][r] = v.y;
            Bs[c4 * 4 + 2][r] = v.z; Bs[c4 * 4 + 3][r] = v.w;
        }
        __syncthreads();
#pragma unroll
        for (int kk = 0; kk < 16; kk++) {
            float a[6], b[8];
#pragma unroll
            for (int i = 0; i < 6; i++) a[i] = As[kk][ty * 6 + i];
#pragma unroll
            for (int j = 0; j < 8; j++) b[j] = Bs[kk][tx * 8 + j];
#pragma unroll
            for (int i = 0; i < 6; i++)
#pragma unroll
                for (int j = 0; j < 8; j++)
                    acc[i][j] = fmaf(a[i], b[j], acc[i][j]);
        }
        __syncthreads();
    }

#pragma unroll
    for (int i = 0; i < 6; i++) {
        const int jg = ty * 6 + i;
        float* dst = VTg + (size_t)(jg >> 4) * DIMV * NCOLS + h * NKV + (jg & 15);
#pragma unroll
        for (int j = 0; j < 8; j++)
            dst[(size_t)(n0 + tx * 8 + j) * NCOLS] = acc[i][j];
    }
}

// ---------------------------------------------------------------------------
// uproj: emits U3 split-3 (hi,hi,lo) directly, coalesced 48B uint4 stores.
// ---------------------------------------------------------------------------
__global__ void __launch_bounds__(256, 2)
uproj_kernel(const float* __restrict__ Kn, const float* __restrict__ Wq,
             const float* __restrict__ gq, __nv_bfloat16* __restrict__ U3)
{
    const int h  = blockIdx.y;
    const int m0 = blockIdx.x * 128;
    const int tid = threadIdx.x;
    const int tx = tid & 15;
    const int ty = tid >> 4;

    __shared__ float As[16][96 + 4];
    __shared__ float Bs[16][128 + 4];

    float acc[6][8];
#pragma unroll
    for (int i = 0; i < 6; i++)
#pragma unroll
        for (int j = 0; j < 8; j++) acc[i][j] = 0.f;

    for (int kc = 0; kc < 8; kc++) {
        const int kbase = h * HD + kc * 16;
#pragma unroll
        for (int it = 0; it < 2; it++) {
            int i = tid + 256 * it;
            if (i < 384) {
                int r = i >> 2, c4 = i & 3;
                float4 v = *(const float4*)(Kn + (size_t)r * DIMV + kbase + c4 * 4);
                float4 g = *(const float4*)(gq + kbase + c4 * 4);
                As[c4 * 4 + 0][r] = v.x * g.x; As[c4 * 4 + 1][r] = v.y * g.y;
                As[c4 * 4 + 2][r] = v.z * g.z; As[c4 * 4 + 3][r] = v.w * g.w;
            }
        }
#pragma unroll
        for (int it = 0; it < 2; it++) {
            int i = tid + 256 * it;
            int kr = i >> 5, c4 = i & 31;
            float4 v = *(const float4*)(Wq + (size_t)(kbase + kr) * DIMV + m0 + c4 * 4);
            Bs[kr][c4 * 4 + 0] = v.x; Bs[kr][c4 * 4 + 1] = v.y;
            Bs[kr][c4 * 4 + 2] = v.z; Bs[kr][c4 * 4 + 3] = v.w;
        }
        __syncthreads();
#pragma unroll
        for (int kk = 0; kk < 16; kk++) {
            float a[6], b[8];
#pragma unroll
            for (int i = 0; i < 6; i++) a[i] = As[kk][ty * 6 + i];
#pragma unroll
            for (int j = 0; j < 8; j++) b[j] = Bs[kk][tx * 8 + j];
#pragma unroll
            for (int i = 0; i < 6; i++)
#pragma unroll
                for (int j = 0; j < 8; j++)
                    acc[i][j] = fmaf(a[i], b[j], acc[i][j]);
        }
        __syncthreads();
    }

#pragma unroll
    for (int i = 0; i < 6; i++) {
        const int jg  = ty * 6 + i;
        const int row = (jg >> 4) * NCOLS + h * NKV + (jg & 15);
        union { __nv_bfloat16 hh[24]; uint4 u[3]; } o;
#pragma unroll
        for (int j = 0; j < 8; j++) {
            float f = acc[i][j];
            __nv_bfloat16 hi = __float2bfloat16(f);
            __nv_bfloat16 lo = __float2bfloat16(f - __bfloat162float(hi));
            o.hh[3*j] = hi; o.hh[3*j+1] = hi; o.hh[3*j+2] = lo;
        }
        uint4* dst = (uint4*)(U3 + (size_t)row * K2 + 3 * (m0 + tx * 8));
        dst[0] = o.u[0]; dst[1] = o.u[1]; dst[2] = o.u[2];
    }
}

__global__ void __launch_bounds__(256)
cb_kernel(const float* __restrict__ Kn, const float* __restrict__ bq,
          const float* __restrict__ gq, float* __restrict__ CB)
{
    int col = blockIdx.x * blockDim.x + threadIdx.x;
    if (col >= NUALL) return;
    int blk = col / NCOLS, rem = col % NCOLS;
    int h = rem >> 4, j = rem & 15;
    int jg = blk * NKV + j;
    const float* kp = Kn + (size_t)jg * DIMV + h * HD;
    const float* bp = bq + h * HD;
    const float* gp = gq + h * HD;
    float s = 0.f;
#pragma unroll 4
    for (int d = 0; d < HD; d++) s = fmaf(bp[d] * gp[d], kp[d], s);
    CB[col] = s;
}

// ---------------------------------------------------------------------------
// softmax: adds cb; ss is in (512)^2-scaled domain
// ---------------------------------------------------------------------------
__global__ void __launch_bounds__(256)
softmax_p3(const float* __restrict__ LG, const float* __restrict__ SS,
           const float* __restrict__ CB, __nv_bfloat16* __restrict__ P3)
{
    int gid = blockIdx.x * blockDim.x + threadIdx.x;
    if (gid >= L1V * NH) return;
    int t = gid / NH, h = gid % NH;
    const int blk = t / HWQ;
    const float s = rsqrtf(SS[t] * (1.0f / (DIMV * SXW2)) + 1e-6f) * 0.08838834764831845f;
    const float* lp = LG + (size_t)t * NCOLS + h * NKV;
    const float* cp = CB + blk * NCOLS + h * NKV;
    float lg[NKV];
#pragma unroll
    for (int j4 = 0; j4 < 4; j4++) {
        float4 v = *(const float4*)(lp + j4 * 4);
        float4 c = *(const float4*)(cp + j4 * 4);
        lg[j4*4+0] = (v.x + c.x) * s; lg[j4*4+1] = (v.y + c.y) * s;
        lg[j4*4+2] = (v.z + c.z) * s; lg[j4*4+3] = (v.w + c.w) * s;
    }
    float m = lg[0];
#pragma unroll
    for (int j = 1; j < NKV; j++) m = fmaxf(m, lg[j]);
    float sum = 0.f;
#pragma unroll
    for (int j = 0; j < NKV; j++) { lg[j] = expf(lg[j] - m); sum += lg[j]; }
    const float inv = 1.f / sum;

    union { __nv_bfloat16 h48[48]; uint4 u[6]; } o;
#pragma unroll
    for (int j = 0; j < NKV; j++) {
        float p = lg[j] * inv;
        __nv_bfloat16 hi = __float2bfloat16(p);
        __nv_bfloat16 lo = __float2bfloat16(p - __bfloat162float(hi));
        o.h48[3*j] = hi; o.h48[3*j+1] = lo; o.h48[3*j+2] = hi;
    }
    uint4* dst = (uint4*)(P3 + (size_t)t * K3P + h * 48);
#pragma unroll
    for (int i = 0; i < 6; i++) dst[i] = o.u[i];
}

// ---------------------------------------------------------------------------
// rmsnorm (in-place) — K only
// ---------------------------------------------------------------------------
__global__ void __launch_bounds__(256)
rmsnorm_rows(float* __restrict__ X, const float* __restrict__ g)
{
    const int row = blockIdx.x;
    float* x = X + (size_t)row * DIMV;

    float ss = 0.f;
    for (int i = threadIdx.x; i < DIMV / 4; i += 256) {
        float4 v = ((const float4*)x)[i];
        ss += v.x * v.x + v.y * v.y + v.z * v.z + v.w * v.w;
    }
#pragma unroll
    for (int o = 16; o > 0; o >>= 1) ss += __shfl_xor_sync(~0u, ss, o);
    __shared__ float red[8];
    if ((threadIdx.x & 31) == 0) red[threadIdx.x >> 5] = ss;
    __syncthreads();
    if (threadIdx.x < 8) {
        float v = red[threadIdx.x];
#pragma unroll
        for (int o = 4; o > 0; o >>= 1) v += __shfl_xor_sync(0xffu, v, o);
        if (threadIdx.x == 0) red[0] = v;
    }
    __syncthreads();
    const float scale = rsqrtf(red[0] * (1.0f / DIMV) + 1e-6f);

    for (int i = threadIdx.x; i < DIMV / 4; i += 256) {
        float4 v  = ((const float4*)x)[i];
        float4 gg = ((const float4*)g)[i];
        v.x *= scale * gg.x; v.y *= scale * gg.y;
        v.z *= scale * gg.z; v.w *= scale * gg.w;
        ((float4*)x)[i] = v;
    }
}

// ---------------------------------------------------------------------------
// launch — round-15 schedule; ONLY change: norm GEMM in e4m3 fp8
// ---------------------------------------------------------------------------
extern "C" void kernel_launch(void* const* d_in, const int* in_sizes, int n_in,
                              void* d_out, int out_size)
{
    (void)in_sizes; (void)n_in; (void)out_size;
    const float* x   = (const float*)d_in[0];
    const float* ctx = (const float*)d_in[1];
    const float* Wq = (const float*)d_in[6];
    const float* bq = (const float*)d_in[7];
    const float* Wk = (const float*)d_in[8];
    const float* bk = (const float*)d_in[9];
    const float* Wv = (const float*)d_in[10];
    const float* bv = (const float*)d_in[11];
    const float* Wo = (const float*)d_in[12];
    const float* bo = (const float*)d_in[13];
    const float* gq = (const float*)d_in[14];
    const float* gk = (const float*)d_in[15];
    float* out = (float*)d_out;

    float *kb, *vb, *vtg, *cb, *ssb, *lgb;
    uint8_t *x8, *w8;
    __nv_bfloat16 *x3, *u3, *p3, *vt3;
    cudaGetSymbolAddress((void**)&kb,  g_k);
    cudaGetSymbolAddress((void**)&vb,  g_v);
    cudaGetSymbolAddress((void**)&vtg, g_vtg);
    cudaGetSymbolAddress((void**)&cb,  g_cb);
    cudaGetSymbolAddress((void**)&ssb, g_ss);
    cudaGetSymbolAddress((void**)&lgb, g_lg);
    cudaGetSymbolAddress((void**)&x8,  g_x8);
    cudaGetSymbolAddress((void**)&w8,  g_w8);
    cudaGetSymbolAddress((void**)&x3,  g_x3);
    cudaGetSymbolAddress((void**)&u3,  g_u3);
    cudaGetSymbolAddress((void**)&p3,  g_p3);
    cudaGetSymbolAddress((void**)&vt3, g_vt3);

    const int dynsmem  = STG * STAGEB;
    const int dynsmem2 = STG2 * STAGE2B;

    static cudaStream_t sB = nullptr;
    static cudaEvent_t  e0 = nullptr, eW = nullptr, eB = nullptr;
    if (sB == nullptr) {
        cudaStreamCreateWithFlags(&sB, cudaStreamNonBlocking);
        cudaEventCreateWithFlags(&e0, cudaEventDisableTiming);
        cudaEventCreateWithFlags(&eW, cudaEventDisableTiming);
        cudaEventCreateWithFlags(&eB, cudaEventDisableTiming);
        cudaFuncSetAttribute(mma_logits_ks, cudaFuncAttributeMaxDynamicSharedMemorySize, dynsmem);
        cudaFuncSetAttribute(mma256_ss8, cudaFuncAttributeMaxDynamicSharedMemorySize, dynsmem2);
        cudaFuncSetAttribute(mma256_z,   cudaFuncAttributeMaxDynamicSharedMemorySize, dynsmem2);
    }

    // fork
    cudaEventRecord(e0, 0);
    cudaStreamWaitEvent(sB, e0, 0);

    // side stream B: zeros + Wq->fp8 first (norm GEMM waits on eW),
    // then the KV prep chain.
    zero_f32<<<1024, 256, 0, sB>>>(ssb, L1V / 4);
    zero_f32<<<2048, 256, 0, sB>>>(lgb, (size_t)L1V * NCOLS / 4);
    cvt_w8<<<2048, 256, 0, sB>>>(Wq, w8, (size_t)DIMV * DIMV / 8);
    cudaEventRecord(eW, sB);
    {
        dim3 grid(DIMV / 128, 1, 2);
        gemm_kv<<<grid, 256, 0, sB>>>(ctx, Wk, bk, kb, Wv, bv, vb, LAV, DIMV, KVDIM);
    }
    rmsnorm_rows<<<LAV, 256, 0, sB>>>(kb, gk);
    {
        dim3 grid(DIMV / 128, NH);
        vproj_kernel<<<grid, 256, 0, sB>>>(vb, Wo, vtg);
        uproj_kernel<<<grid, 256, 0, sB>>>(kb, Wq, gq, u3);
    }
    cb_kernel<<<(NUALL + 255) / 256, 256, 0, sB>>>(kb, bq, gq, cb);
    cvt_split3<1><<<2048, 256, 0, sB>>>(vtg, vt3, (size_t)NBLK * DIMV * NCOLS / 8);
    cudaEventRecord(eB, sB);

    // main: x conversion + fp8 norm GEMM
    cvt_x_fused<<<2048, 256>>>(x, x8, x3, (size_t)L1V * DIMV / 8);
    cudaStreamWaitEvent(0, eW, 0);
    {
        dim3 grid(DIMV / 256, (L1V + 127) / 128);
        mma256_ss8<<<grid, 256, dynsmem2>>>(x8, w8, bq, ssb, L1V, DIMV, DIMV);
    }

    // join, then K-split logits -> softmax(+cb) -> P@VT
    cudaStreamWaitEvent(0, eB, 0);
    {
        dim3 grid(NCOLS / 128, (HWQ + 127) / 128, NBLK * NKSPL);
        mma_logits_ks<<<grid, 256, dynsmem>>>(x3, u3, lgb);
    }
    softmax_p3<<<(L1V * NH + 255) / 256, 256>>>(lgb, ssb, cb, p3);
    {
        dim3 grid(DIMV / 256, (HWQ + 127) / 128, NBLK);
        mma256_z<<<grid, 256, dynsmem2>>>(
            p3, vt3, bo, out, HWQ, DIMV, K3P,
            (size_t)HWQ * K3P, (size_t)DIMV * K3P, (size_t)HWQ * DIMV);
    }
}